// round 1
// baseline (speedup 1.0000x reference)
#include <cuda_runtime.h>
#include <math.h>

// ---- model constants ----
#define BB   2
#define TT   1024
#define RR   2048          // BB*TT rows
#define DD   768
#define HH   12
#define KVHH 4
#define HDD  64
#define KVD  256
#define LLAY 6
#define VV   32000
#define FF   3072

// ---- scratch (static device globals; no runtime allocation) ----
__device__ float g_x [RR*DD];
__device__ float g_x0[RR*DD];
__device__ float g_xn[RR*DD];
__device__ float g_q [RR*DD];
__device__ float g_k [RR*KVD];
__device__ float g_v [RR*KVD];
__device__ float g_y [RR*DD];
__device__ float g_h [RR*FF];

// ------------------------------------------------------------------
// helpers
// ------------------------------------------------------------------
__device__ __forceinline__ float block_reduce_sum_256(float v, float* sh) {
    int tid = threadIdx.x;
    sh[tid] = v;
    __syncthreads();
    #pragma unroll
    for (int s = 128; s > 0; s >>= 1) {
        if (tid < s) sh[tid] += sh[tid + s];
        __syncthreads();
    }
    return sh[0];
}

__device__ __forceinline__ float warp_reduce_sum(float v) {
    #pragma unroll
    for (int o = 16; o > 0; o >>= 1)
        v += __shfl_xor_sync(0xffffffffu, v, o);
    return v;
}

// ------------------------------------------------------------------
// embedding + rmsnorm:  x = x0 = norm(wte[idx])
// grid RR blocks x 256 threads
// ------------------------------------------------------------------
__global__ void embed_norm_kernel(const int* __restrict__ idx,
                                  const float* __restrict__ wte) {
    __shared__ float sh[256];
    int row = blockIdx.x;
    int tid = threadIdx.x;
    int tok = idx[row];
    const float* wrow = wte + (size_t)tok * DD;
    float v[3]; float ss = 0.f;
    #pragma unroll
    for (int j = 0; j < 3; ++j) {
        v[j] = wrow[tid + j*256];
        ss += v[j]*v[j];
    }
    float tot = block_reduce_sum_256(ss, sh);
    float sc = rsqrtf(tot * (1.0f/DD) + 1e-6f);
    #pragma unroll
    for (int j = 0; j < 3; ++j) {
        float o = v[j] * sc;
        g_x [(size_t)row*DD + tid + j*256] = o;
        g_x0[(size_t)row*DD + tid + j*256] = o;
    }
}

// ------------------------------------------------------------------
// residual mix + rmsnorm.
// li >= 0:  x = rl[li]*x + xl[li]*x0 (written back); xn = norm(x)
// li <  0:  xn = norm(x)   (x untouched)
// ------------------------------------------------------------------
__global__ void resid_norm_kernel(const float* __restrict__ rl,
                                  const float* __restrict__ xl,
                                  int li) {
    __shared__ float sh[256];
    int row = blockIdx.x;
    int tid = threadIdx.x;
    float rs = 1.f, xs = 0.f;
    if (li >= 0) { rs = rl[li]; xs = xl[li]; }
    float v[3]; float ss = 0.f;
    #pragma unroll
    for (int j = 0; j < 3; ++j) {
        size_t i = (size_t)row*DD + tid + j*256;
        float val = g_x[i]*rs;
        if (li >= 0) val += g_x0[i]*xs;
        v[j] = val;
        ss += val*val;
    }
    float tot = block_reduce_sum_256(ss, sh);
    float sc = rsqrtf(tot * (1.0f/DD) + 1e-6f);
    #pragma unroll
    for (int j = 0; j < 3; ++j) {
        size_t i = (size_t)row*DD + tid + j*256;
        if (li >= 0) g_x[i] = v[j];
        g_xn[i] = v[j]*sc;
    }
}

// ------------------------------------------------------------------
// generic tiled GEMM:  C[M,N] (+)= A[M,K] * B[N,K]^T
// A,B row-major K-contiguous.  M%128==0, N%64==0, K%16==0.
// EPI: 0 store, 1 accumulate, 2 relu^2, 3 softcap 15*tanh(x/15)
// grid (N/64, M/128), 256 threads
// ------------------------------------------------------------------
template<int EPI>
__global__ void __launch_bounds__(256)
gemm_nt_kernel(const float* __restrict__ A, const float* __restrict__ B,
               float* __restrict__ C, int M, int N, int K) {
    __shared__ float As[16][132];
    __shared__ float Bs[16][68];
    int tid = threadIdx.x;
    int bm = blockIdx.y * 128;
    int bn = blockIdx.x * 64;
    int ty = tid >> 4;       // 0..15 -> 8 rows each
    int tx = tid & 15;       // 0..15 -> 4 cols each
    float acc[8][4];
    #pragma unroll
    for (int i = 0; i < 8; ++i)
        #pragma unroll
        for (int j = 0; j < 4; ++j) acc[i][j] = 0.f;

    const float* Ab = A + (size_t)bm * K;
    const float* Bb = B + (size_t)bn * K;

    for (int k0 = 0; k0 < K; k0 += 16) {
        #pragma unroll
        for (int i = 0; i < 2; ++i) {
            int id = tid + i*256;
            int m  = id >> 2;
            int kq = (id & 3) << 2;
            float4 va = *reinterpret_cast<const float4*>(Ab + (size_t)m*K + k0 + kq);
            As[kq+0][m] = va.x; As[kq+1][m] = va.y;
            As[kq+2][m] = va.z; As[kq+3][m] = va.w;
        }
        {
            int n  = tid >> 2;
            int kq = (tid & 3) << 2;
            float4 vb = *reinterpret_cast<const float4*>(Bb + (size_t)n*K + k0 + kq);
            Bs[kq+0][n] = vb.x; Bs[kq+1][n] = vb.y;
            Bs[kq+2][n] = vb.z; Bs[kq+3][n] = vb.w;
        }
        __syncthreads();
        #pragma unroll
        for (int kk = 0; kk < 16; ++kk) {
            float a[8], b[4];
            float4 a0 = *reinterpret_cast<const float4*>(&As[kk][ty*8]);
            float4 a1 = *reinterpret_cast<const float4*>(&As[kk][ty*8+4]);
            a[0]=a0.x; a[1]=a0.y; a[2]=a0.z; a[3]=a0.w;
            a[4]=a1.x; a[5]=a1.y; a[6]=a1.z; a[7]=a1.w;
            float4 b0 = *reinterpret_cast<const float4*>(&Bs[kk][tx*4]);
            b[0]=b0.x; b[1]=b0.y; b[2]=b0.z; b[3]=b0.w;
            #pragma unroll
            for (int i = 0; i < 8; ++i)
                #pragma unroll
                for (int j = 0; j < 4; ++j)
                    acc[i][j] = fmaf(a[i], b[j], acc[i][j]);
        }
        __syncthreads();
    }

    #pragma unroll
    for (int i = 0; i < 8; ++i) {
        size_t crow = (size_t)(bm + ty*8 + i) * N + bn + tx*4;
        #pragma unroll
        for (int j = 0; j < 4; ++j) {
            float val = acc[i][j];
            if (EPI == 1) {
                C[crow + j] += val;
            } else if (EPI == 2) {
                float r = fmaxf(val, 0.f);
                C[crow + j] = r * r;
            } else if (EPI == 3) {
                C[crow + j] = 15.0f * tanhf(val * (1.0f/15.0f));
            } else {
                C[crow + j] = val;
            }
        }
    }
}

// ------------------------------------------------------------------
// value-embedding gate:  v += 2*sigmoid(xn[:, :32] . gate_w[h]) * ve_table[idx]
// grid RR blocks x 256 threads
// ------------------------------------------------------------------
__global__ void ve_kernel(const int* __restrict__ idx,
                          const float* __restrict__ ve_table,   // [VV, KVD]
                          const float* __restrict__ gate_w) {   // [KVHH, 32]
    __shared__ float gates[KVHH];
    int row = blockIdx.x;
    int tid = threadIdx.x;
    if (tid < KVHH*32) {
        int g = tid >> 5, lane = tid & 31;
        float p = g_xn[(size_t)row*DD + lane] * gate_w[g*32 + lane];
        p = warp_reduce_sum(p);
        if (lane == 0) gates[g] = 2.0f / (1.0f + expf(-p));
    }
    __syncthreads();
    int tok = idx[row];
    g_v[(size_t)row*KVD + tid] += gates[tid >> 6] *
        ve_table[(size_t)tok*KVD + tid];
}

// ------------------------------------------------------------------
// RoPE + per-head rmsnorm.  One warp per (row, head).  HD=64: lane owns
// element (lane) and (lane+32) == the rotation pair.
// ------------------------------------------------------------------
__global__ void rope_norm_kernel(float* __restrict__ p, int nh) {
    int gw   = (blockIdx.x * blockDim.x + threadIdx.x) >> 5;
    int lane = threadIdx.x & 31;
    int row  = gw / nh;
    int head = gw - row*nh;
    int t    = row & (TT-1);
    float* base = p + (size_t)row*nh*HDD + head*HDD;
    float a = base[lane];
    float b = base[lane + 32];
    float inv = 1.0f / powf(10000.0f, (float)lane * (1.0f/32.0f));
    float ang = (float)t * inv;
    float s, c;
    sincosf(ang, &s, &c);
    float na =  a*c + b*s;
    float nb = -a*s + b*c;
    float ss = warp_reduce_sum(na*na + nb*nb);
    float sc = rsqrtf(ss * (1.0f/HDD) + 1e-6f);
    base[lane]      = na * sc;
    base[lane + 32] = nb * sc;
}

// ------------------------------------------------------------------
// attention: one warp per (b, h, t) query.  Online softmax over the
// sliding window [t-w+1, t].  GQA: q head h uses kv head h/3.
// ------------------------------------------------------------------
__global__ void attn_kernel(int w) {
    int gw   = (blockIdx.x * blockDim.x + threadIdx.x) >> 5;
    int lane = threadIdx.x & 31;
    int h    = gw % HH;
    int row  = gw / HH;          // b*TT + t
    int b    = row / TT;
    int t    = row & (TT-1);
    int g    = h / (HH / KVHH);

    const float* qp = g_q + (size_t)row*DD + h*HDD;
    float q0 = qp[lane], q1 = qp[lane + 32];

    float m = -INFINITY, l = 0.f, a0 = 0.f, a1 = 0.f;
    int lo = t - w + 1; if (lo < 0) lo = 0;
    for (int j = lo; j <= t; ++j) {
        size_t kvoff = ((size_t)(b*TT + j))*KVD + g*HDD;
        float s = q0*g_k[kvoff + lane] + q1*g_k[kvoff + lane + 32];
        s = warp_reduce_sum(s);
        s *= 0.125f;                     // 1/sqrt(64)
        float nm   = fmaxf(m, s);
        float corr = expf(m - nm);       // expf(-inf)=0 on first iter
        float pr   = expf(s - nm);
        l  = l *corr + pr;
        a0 = a0*corr + pr*g_v[kvoff + lane];
        a1 = a1*corr + pr*g_v[kvoff + lane + 32];
        m = nm;
    }
    float invl = 1.0f / l;
    g_y[(size_t)row*DD + h*HDD + lane]      = a0 * invl;
    g_y[(size_t)row*DD + h*HDD + lane + 32] = a1 * invl;
}

// ------------------------------------------------------------------
// host launcher
// ------------------------------------------------------------------
extern "C" void kernel_launch(void* const* d_in, const int* in_sizes, int n_in,
                              void* d_out, int out_size) {
    (void)in_sizes; (void)n_in; (void)out_size;
    const int*   idx    = (const int*)  d_in[0];
    const float* wte    = (const float*)d_in[1];
    const float* Wq     = (const float*)d_in[2];
    const float* Wk     = (const float*)d_in[3];
    const float* Wv     = (const float*)d_in[4];
    const float* Wo     = (const float*)d_in[5];
    const float* Wfc    = (const float*)d_in[6];
    const float* Wproj  = (const float*)d_in[7];
    const float* vetab  = (const float*)d_in[8];
    const float* vegate = (const float*)d_in[9];
    const float* rl     = (const float*)d_in[10];
    const float* xl     = (const float*)d_in[11];
    const float* lm     = (const float*)d_in[12];
    float* out = (float*)d_out;

    float *px, *pxn, *pq, *pk, *pv, *py, *ph;
    cudaGetSymbolAddress((void**)&px,  g_x);
    cudaGetSymbolAddress((void**)&pxn, g_xn);
    cudaGetSymbolAddress((void**)&pq,  g_q);
    cudaGetSymbolAddress((void**)&pk,  g_k);
    cudaGetSymbolAddress((void**)&pv,  g_v);
    cudaGetSymbolAddress((void**)&py,  g_y);
    cudaGetSymbolAddress((void**)&ph,  g_h);

    const int windows[LLAY] = {TT/2, TT, TT/2, TT, TT/2, TT};

    embed_norm_kernel<<<RR, 256>>>(idx, wte);

    for (int i = 0; i < LLAY; ++i) {
        resid_norm_kernel<<<RR, 256>>>(rl, xl, i);

        gemm_nt_kernel<0><<<dim3(DD/64,  RR/128), 256>>>(pxn, Wq + (size_t)i*DD*DD,  pq, RR, DD,  DD);
        gemm_nt_kernel<0><<<dim3(KVD/64, RR/128), 256>>>(pxn, Wk + (size_t)i*KVD*DD, pk, RR, KVD, DD);
        gemm_nt_kernel<0><<<dim3(KVD/64, RR/128), 256>>>(pxn, Wv + (size_t)i*KVD*DD, pv, RR, KVD, DD);

        int slot = (i == 1) ? 0 : (i == 3) ? 1 : (i == 5) ? 2 : -1;
        if (slot >= 0) {
            ve_kernel<<<RR, 256>>>(idx,
                                   vetab  + (size_t)slot*VV*KVD,
                                   vegate + (size_t)slot*KVHH*32);
        }

        rope_norm_kernel<<<(RR*HH)/8,   256>>>(pq, HH);
        rope_norm_kernel<<<(RR*KVHH)/8, 256>>>(pk, KVHH);

        attn_kernel<<<(RR*HH)/8, 256>>>(windows[i]);

        gemm_nt_kernel<1><<<dim3(DD/64, RR/128), 256>>>(py, Wo + (size_t)i*DD*DD, px, RR, DD, DD);

        resid_norm_kernel<<<RR, 256>>>(rl, xl, -1);

        gemm_nt_kernel<2><<<dim3(FF/64, RR/128), 256>>>(pxn, Wfc   + (size_t)i*FF*DD, ph, RR, FF, DD);
        gemm_nt_kernel<1><<<dim3(DD/64, RR/128), 256>>>(ph,  Wproj + (size_t)i*DD*FF, px, RR, DD, FF);
    }

    resid_norm_kernel<<<RR, 256>>>(rl, xl, -1);
    gemm_nt_kernel<3><<<dim3(VV/64, RR/128), 256>>>(pxn, lm, out, RR, VV, DD);
}

// round 2
// speedup vs baseline: 1.2317x; 1.2317x over previous
#include <cuda_runtime.h>
#include <cuda_bf16.h>
#include <math.h>
#include <stdint.h>

// ---- model constants ----
#define BB   2
#define TT   1024
#define RR   2048          // BB*TT rows
#define DD   768
#define HH   12
#define KVHH 4
#define HDD  64
#define QKVW 1280          // 768 q + 256 k + 256 v
#define LLAY 6
#define VV   32000
#define FF   3072

// ---- scratch (static device globals; no runtime allocation) ----
__device__ float g_x   [RR*DD];
__device__ float g_x0  [RR*DD];
__device__ float g_xn  [RR*DD];
__device__ float g_qkv [RR*QKVW];
__device__ float g_y   [RR*DD];
__device__ float g_h   [RR*FF];
__device__ float g_wqkv[LLAY*QKVW*DD];   // packed Wq|Wk|Wv per layer

// ------------------------------------------------------------------
// helpers
// ------------------------------------------------------------------
__device__ __forceinline__ float block_reduce_sum_256(float v, float* sh) {
    int tid = threadIdx.x;
    sh[tid] = v;
    __syncthreads();
    #pragma unroll
    for (int s = 128; s > 0; s >>= 1) {
        if (tid < s) sh[tid] += sh[tid + s];
        __syncthreads();
    }
    return sh[0];
}

__device__ __forceinline__ float warp_reduce_sum(float v) {
    #pragma unroll
    for (int o = 16; o > 0; o >>= 1)
        v += __shfl_xor_sync(0xffffffffu, v, o);
    return v;
}
__device__ __forceinline__ float warp_reduce_max(float v) {
    #pragma unroll
    for (int o = 16; o > 0; o >>= 1)
        v = fmaxf(v, __shfl_xor_sync(0xffffffffu, v, o));
    return v;
}

// ------------------------------------------------------------------
// pack Wq|Wk|Wv -> g_wqkv  (6 * 1280 * 768 elements)
// ------------------------------------------------------------------
__global__ void pack_qkv_kernel(const float* __restrict__ Wq,
                                const float* __restrict__ Wk,
                                const float* __restrict__ Wv) {
    int i = blockIdx.x * blockDim.x + threadIdx.x;
    const int total = LLAY * QKVW * DD;
    if (i >= total) return;
    int c = i % DD;
    int r = (i / DD) % QKVW;
    int l = i / (DD * QKVW);
    float v;
    if (r < DD)            v = Wq[(size_t)l*DD*DD        + (size_t)r*DD        + c];
    else if (r < DD + 256) v = Wk[(size_t)l*256*DD       + (size_t)(r-DD)*DD   + c];
    else                   v = Wv[(size_t)l*256*DD       + (size_t)(r-DD-256)*DD + c];
    g_wqkv[i] = v;
}

// ------------------------------------------------------------------
// embedding + rmsnorm:  x = x0 = norm(wte[idx])
// ------------------------------------------------------------------
__global__ void embed_norm_kernel(const int* __restrict__ idx,
                                  const float* __restrict__ wte) {
    __shared__ float sh[256];
    int row = blockIdx.x;
    int tid = threadIdx.x;
    int tok = idx[row];
    const float* wrow = wte + (size_t)tok * DD;
    float v[3]; float ss = 0.f;
    #pragma unroll
    for (int j = 0; j < 3; ++j) {
        v[j] = wrow[tid + j*256];
        ss += v[j]*v[j];
    }
    float tot = block_reduce_sum_256(ss, sh);
    float sc = rsqrtf(tot * (1.0f/DD) + 1e-6f);
    #pragma unroll
    for (int j = 0; j < 3; ++j) {
        float o = v[j] * sc;
        g_x [(size_t)row*DD + tid + j*256] = o;
        g_x0[(size_t)row*DD + tid + j*256] = o;
    }
}

// ------------------------------------------------------------------
// residual mix + rmsnorm
// ------------------------------------------------------------------
__global__ void resid_norm_kernel(const float* __restrict__ rl,
                                  const float* __restrict__ xl,
                                  int li) {
    __shared__ float sh[256];
    int row = blockIdx.x;
    int tid = threadIdx.x;
    float rs = 1.f, xs = 0.f;
    if (li >= 0) { rs = rl[li]; xs = xl[li]; }
    float v[3]; float ss = 0.f;
    #pragma unroll
    for (int j = 0; j < 3; ++j) {
        size_t i = (size_t)row*DD + tid + j*256;
        float val = g_x[i]*rs;
        if (li >= 0) val += g_x0[i]*xs;
        v[j] = val;
        ss += val*val;
    }
    float tot = block_reduce_sum_256(ss, sh);
    float sc = rsqrtf(tot * (1.0f/DD) + 1e-6f);
    #pragma unroll
    for (int j = 0; j < 3; ++j) {
        size_t i = (size_t)row*DD + tid + j*256;
        if (li >= 0) g_x[i] = v[j];
        g_xn[i] = v[j]*sc;
    }
}

// ------------------------------------------------------------------
// bf16x3 tensor-core GEMM:  C[M,N] (+)= A[M,K] * B[N,K]^T   (fp32 in/out)
// Split each operand into bf16 hi+lo; accumulate hi*hi + hi*lo + lo*hi.
// 128x128 tile, BK=32, 256 threads (8 warps as 2x4, warp tile 64x32).
// EPI: 0 store, 1 accumulate, 2 relu^2, 3 softcap 15*tanh(x/15)
// ------------------------------------------------------------------
#define MMA_BF16(d, a, b)                                                     \
    asm volatile("mma.sync.aligned.m16n8k16.row.col.f32.bf16.bf16.f32 "       \
                 "{%0,%1,%2,%3},{%4,%5,%6,%7},{%8,%9},{%0,%1,%2,%3};"         \
                 : "+f"(d[0]), "+f"(d[1]), "+f"(d[2]), "+f"(d[3])             \
                 : "r"(a[0]), "r"(a[1]), "r"(a[2]), "r"(a[3]),                \
                   "r"(b[0]), "r"(b[1]));

__device__ __forceinline__ void split4(float4 v, __nv_bfloat16* ph, __nv_bfloat16* pl) {
    __nv_bfloat162 h0, h1, l0, l1;
    h0.x = __float2bfloat16_rn(v.x);
    h0.y = __float2bfloat16_rn(v.y);
    h1.x = __float2bfloat16_rn(v.z);
    h1.y = __float2bfloat16_rn(v.w);
    l0.x = __float2bfloat16_rn(v.x - __bfloat162float(h0.x));
    l0.y = __float2bfloat16_rn(v.y - __bfloat162float(h0.y));
    l1.x = __float2bfloat16_rn(v.z - __bfloat162float(h1.x));
    l1.y = __float2bfloat16_rn(v.w - __bfloat162float(h1.y));
    *(__nv_bfloat162*)(ph)     = h0;
    *(__nv_bfloat162*)(ph + 2) = h1;
    *(__nv_bfloat162*)(pl)     = l0;
    *(__nv_bfloat162*)(pl + 2) = l1;
}

template<int EPI>
__global__ void __launch_bounds__(256)
gemm_bf16x3_kernel(const float* __restrict__ A, const float* __restrict__ B,
                   float* __restrict__ C, int M, int N, int K) {
    __shared__ __nv_bfloat16 sAh[128][40];
    __shared__ __nv_bfloat16 sAl[128][40];
    __shared__ __nv_bfloat16 sBh[128][40];
    __shared__ __nv_bfloat16 sBl[128][40];

    int tid  = threadIdx.x;
    int lane = tid & 31;
    int warp = tid >> 5;
    int wm   = warp & 1;       // 0..1 -> m offset *64
    int wn   = warp >> 1;      // 0..3 -> n offset *32
    int bm   = blockIdx.y * 128;
    int bn   = blockIdx.x * 128;

    float acc[4][4][4];
    #pragma unroll
    for (int i = 0; i < 4; ++i)
        #pragma unroll
        for (int j = 0; j < 4; ++j)
            #pragma unroll
            for (int r = 0; r < 4; ++r) acc[i][j][r] = 0.f;

    int fr = lane >> 2;          // 0..7
    int fq = (lane & 3) << 1;    // 0,2,4,6

    for (int k0 = 0; k0 < K; k0 += 32) {
        // load + split A, B tiles (128x32 fp32 each)
        #pragma unroll
        for (int it = 0; it < 4; ++it) {
            int id  = tid + it*256;     // 0..1023
            int row = id >> 3;
            int kq  = (id & 7) << 2;
            float4 va = *(const float4*)(A + (size_t)(bm + row)*K + k0 + kq);
            split4(va, &sAh[row][kq], &sAl[row][kq]);
            float4 vb = *(const float4*)(B + (size_t)(bn + row)*K + k0 + kq);
            split4(vb, &sBh[row][kq], &sBl[row][kq]);
        }
        __syncthreads();

        #pragma unroll
        for (int kc = 0; kc < 32; kc += 16) {
            uint32_t ah[4][4], al[4][4], bh[4][2], bl[4][2];
            #pragma unroll
            for (int mi = 0; mi < 4; ++mi) {
                int row = wm*64 + mi*16 + fr;
                ah[mi][0] = *(const uint32_t*)&sAh[row  ][kc+fq];
                ah[mi][1] = *(const uint32_t*)&sAh[row+8][kc+fq];
                ah[mi][2] = *(const uint32_t*)&sAh[row  ][kc+fq+8];
                ah[mi][3] = *(const uint32_t*)&sAh[row+8][kc+fq+8];
                al[mi][0] = *(const uint32_t*)&sAl[row  ][kc+fq];
                al[mi][1] = *(const uint32_t*)&sAl[row+8][kc+fq];
                al[mi][2] = *(const uint32_t*)&sAl[row  ][kc+fq+8];
                al[mi][3] = *(const uint32_t*)&sAl[row+8][kc+fq+8];
            }
            #pragma unroll
            for (int ni = 0; ni < 4; ++ni) {
                int nr = wn*32 + ni*8 + fr;
                bh[ni][0] = *(const uint32_t*)&sBh[nr][kc+fq];
                bh[ni][1] = *(const uint32_t*)&sBh[nr][kc+fq+8];
                bl[ni][0] = *(const uint32_t*)&sBl[nr][kc+fq];
                bl[ni][1] = *(const uint32_t*)&sBl[nr][kc+fq+8];
            }
            #pragma unroll
            for (int mi = 0; mi < 4; ++mi)
                #pragma unroll
                for (int ni = 0; ni < 4; ++ni) {
                    MMA_BF16(acc[mi][ni], ah[mi], bh[ni]);
                    MMA_BF16(acc[mi][ni], ah[mi], bl[ni]);
                    MMA_BF16(acc[mi][ni], al[mi], bh[ni]);
                }
        }
        __syncthreads();
    }

    // epilogue
    #pragma unroll
    for (int mi = 0; mi < 4; ++mi) {
        #pragma unroll
        for (int ni = 0; ni < 4; ++ni) {
            int row = bm + wm*64 + mi*16 + fr;
            int col = bn + wn*32 + ni*8 + fq;
            #pragma unroll
            for (int r = 0; r < 4; ++r) {
                int rr = row + (r >> 1)*8;
                int cc = col + (r & 1);
                float val = acc[mi][ni][r];
                size_t ix = (size_t)rr * N + cc;
                if (EPI == 1) {
                    C[ix] += val;
                } else if (EPI == 2) {
                    float re = fmaxf(val, 0.f);
                    C[ix] = re * re;
                } else if (EPI == 3) {
                    C[ix] = 15.0f * tanhf(val * (1.0f/15.0f));
                } else {
                    C[ix] = val;
                }
            }
        }
    }
}

// ------------------------------------------------------------------
// value-embedding gate:  v += 2*sigmoid(xn[:, :32] . gate_w[h]) * ve_table[idx]
// v lives in g_qkv at column offset 1024.
// ------------------------------------------------------------------
__global__ void ve_kernel(const int* __restrict__ idx,
                          const float* __restrict__ ve_table,   // [VV, 256]
                          const float* __restrict__ gate_w) {   // [KVHH, 32]
    __shared__ float gates[KVHH];
    int row = blockIdx.x;
    int tid = threadIdx.x;
    if (tid < KVHH*32) {
        int g = tid >> 5, lane = tid & 31;
        float p = g_xn[(size_t)row*DD + lane] * gate_w[g*32 + lane];
        p = warp_reduce_sum(p);
        if (lane == 0) gates[g] = 2.0f / (1.0f + expf(-p));
    }
    __syncthreads();
    int tok = idx[row];
    g_qkv[(size_t)row*QKVW + 1024 + tid] += gates[tid >> 6] *
        ve_table[(size_t)tok*256 + tid];
}

// ------------------------------------------------------------------
// RoPE + per-head rmsnorm.  One warp per (row, head).
// base = p + row*rs + head*64
// ------------------------------------------------------------------
__global__ void rope_norm_kernel(float* __restrict__ p, int nh, int rs) {
    int gw   = (blockIdx.x * blockDim.x + threadIdx.x) >> 5;
    int lane = threadIdx.x & 31;
    int row  = gw / nh;
    int head = gw - row*nh;
    int t    = row & (TT-1);
    float* base = p + (size_t)row*rs + head*HDD;
    float a = base[lane];
    float b = base[lane + 32];
    float inv = 1.0f / powf(10000.0f, (float)lane * (1.0f/32.0f));
    float ang = (float)t * inv;
    float s, c;
    sincosf(ang, &s, &c);
    float na =  a*c + b*s;
    float nb = -a*s + b*c;
    float ss = warp_reduce_sum(na*na + nb*nb);
    float sc = rsqrtf(ss * (1.0f/HDD) + 1e-6f);
    base[lane]      = na * sc;
    base[lane + 32] = nb * sc;
}

// ------------------------------------------------------------------
// attention: one warp per (b, h, t) query, lane-per-key chunked scoring.
// q/k/v all in g_qkv (row stride 1280; q@0, k@768, v@1024). out -> g_y.
// ------------------------------------------------------------------
__global__ void attn_kernel(int w) {
    __shared__ float qs[8][64];
    int wid  = threadIdx.x >> 5;
    int lane = threadIdx.x & 31;
    int gw   = blockIdx.x * 8 + wid;
    int h    = gw % HH;
    int row  = gw / HH;          // b*TT + t
    int b    = row >> 10;
    int t    = row & (TT-1);
    int g    = h / (HH / KVHH);

    const float* qp = g_qkv + (size_t)row*QKVW + h*HDD;
    float* qw = qs[wid];
    qw[lane]      = qp[lane];
    qw[lane + 32] = qp[lane + 32];
    __syncwarp();

    float m = -INFINITY, l = 0.f, a0 = 0.f, a1 = 0.f;
    int lo = t - w + 1; if (lo < 0) lo = 0;

    for (int j0 = lo; j0 <= t; j0 += 32) {
        int key = j0 + lane;
        float s = -INFINITY;
        if (key <= t) {
            const float* kp = g_qkv + (size_t)(b*TT + key)*QKVW + DD + g*HDD;
            float d = 0.f;
            #pragma unroll
            for (int di = 0; di < 64; di += 4) {
                float4 kv = *(const float4*)(kp + di);
                d += qw[di]*kv.x + qw[di+1]*kv.y + qw[di+2]*kv.z + qw[di+3]*kv.w;
            }
            s = d * 0.125f;
        }
        float cm = warp_reduce_max(s);
        float nm = fmaxf(m, cm);
        float p  = expf(s - nm);          // 0 for masked lanes
        float corr = expf(m - nm);        // 0 on first chunk
        float sl = warp_reduce_sum(p);
        l  = l*corr + sl;
        a0 *= corr;
        a1 *= corr;

        const float* vbase = g_qkv + (size_t)(b*TT + j0)*QKVW + 1024 + g*HDD;
        int nk = t - j0 + 1; if (nk > 32) nk = 32;
        for (int jj = 0; jj < nk; ++jj) {
            float pj = __shfl_sync(0xffffffffu, p, jj);
            const float* vp = vbase + (size_t)jj*QKVW;
            a0 = fmaf(pj, vp[lane],      a0);
            a1 = fmaf(pj, vp[lane + 32], a1);
        }
        m = nm;
    }
    float invl = 1.0f / l;
    g_y[(size_t)row*DD + h*HDD + lane]      = a0 * invl;
    g_y[(size_t)row*DD + h*HDD + lane + 32] = a1 * invl;
}

// ------------------------------------------------------------------
// host launcher
// ------------------------------------------------------------------
extern "C" void kernel_launch(void* const* d_in, const int* in_sizes, int n_in,
                              void* d_out, int out_size) {
    (void)in_sizes; (void)n_in; (void)out_size;
    const int*   idx    = (const int*)  d_in[0];
    const float* wte    = (const float*)d_in[1];
    const float* Wq     = (const float*)d_in[2];
    const float* Wk     = (const float*)d_in[3];
    const float* Wv     = (const float*)d_in[4];
    const float* Wo     = (const float*)d_in[5];
    const float* Wfc    = (const float*)d_in[6];
    const float* Wproj  = (const float*)d_in[7];
    const float* vetab  = (const float*)d_in[8];
    const float* vegate = (const float*)d_in[9];
    const float* rl     = (const float*)d_in[10];
    const float* xl     = (const float*)d_in[11];
    const float* lm     = (const float*)d_in[12];
    float* out = (float*)d_out;

    float *px, *pxn, *pqkv, *py, *ph, *pwqkv;
    cudaGetSymbolAddress((void**)&px,    g_x);
    cudaGetSymbolAddress((void**)&pxn,   g_xn);
    cudaGetSymbolAddress((void**)&pqkv,  g_qkv);
    cudaGetSymbolAddress((void**)&py,    g_y);
    cudaGetSymbolAddress((void**)&ph,    g_h);
    cudaGetSymbolAddress((void**)&pwqkv, g_wqkv);

    const int windows[LLAY] = {TT/2, TT, TT/2, TT, TT/2, TT};

    {
        int total = LLAY * QKVW * DD;
        pack_qkv_kernel<<<(total + 255)/256, 256>>>(Wq, Wk, Wv);
    }
    embed_norm_kernel<<<RR, 256>>>(idx, wte);

    for (int i = 0; i < LLAY; ++i) {
        resid_norm_kernel<<<RR, 256>>>(rl, xl, i);

        // fused QKV: C[2048,1280] = xn * WqkvT
        gemm_bf16x3_kernel<0><<<dim3(QKVW/128, RR/128), 256>>>(
            pxn, pwqkv + (size_t)i*QKVW*DD, pqkv, RR, QKVW, DD);

        int slot = (i == 1) ? 0 : (i == 3) ? 1 : (i == 5) ? 2 : -1;
        if (slot >= 0) {
            ve_kernel<<<RR, 256>>>(idx,
                                   vetab  + (size_t)slot*VV*256,
                                   vegate + (size_t)slot*KVHH*32);
        }

        rope_norm_kernel<<<(RR*HH)/8,   256>>>(pqkv,       HH,   QKVW);
        rope_norm_kernel<<<(RR*KVHH)/8, 256>>>(pqkv + DD,  KVHH, QKVW);

        attn_kernel<<<(RR*HH)/8, 256>>>(windows[i]);

        gemm_bf16x3_kernel<1><<<dim3(DD/128, RR/128), 256>>>(
            py, Wo + (size_t)i*DD*DD, px, RR, DD, DD);

        resid_norm_kernel<<<RR, 256>>>(rl, xl, -1);

        gemm_bf16x3_kernel<2><<<dim3(FF/128, RR/128), 256>>>(
            pxn, Wfc + (size_t)i*FF*DD, ph, RR, FF, DD);
        gemm_bf16x3_kernel<1><<<dim3(DD/128, RR/128), 256>>>(
            ph, Wproj + (size_t)i*DD*FF, px, RR, DD, FF);
    }

    resid_norm_kernel<<<RR, 256>>>(rl, xl, -1);
    gemm_bf16x3_kernel<3><<<dim3(VV/128, RR/128), 256>>>(
        pxn, lm, out, RR, VV, DD);
}

// round 3
// speedup vs baseline: 2.0976x; 1.7030x over previous
#include <cuda_runtime.h>
#include <cuda_bf16.h>
#include <math.h>
#include <stdint.h>

// ---- model constants ----
#define BB   2
#define TT   1024
#define RR   2048          // BB*TT rows
#define DD   768
#define HH   12
#define KVHH 4
#define HDD  64
#define QKVW 1280          // 768 q + 256 k + 256 v
#define LLAY 6
#define VV   32000
#define FF   3072

typedef __nv_bfloat16 bf16;
typedef __nv_bfloat162 bf162;

// ---- scratch (static device globals; no runtime allocation) ----
__device__ float g_x  [RR*DD];
__device__ float g_x0 [RR*DD];
__device__ float g_xn [RR*DD];
__device__ float g_qkv[RR*QKVW];

__device__ bf16 g_xnh[RR*DD],  g_xnl[RR*DD];
__device__ bf16 g_yh [RR*DD],  g_yl [RR*DD];
__device__ bf16 g_hh [RR*FF],  g_hl [RR*FF];

__device__ bf16 g_wqkvh[LLAY*QKVW*DD], g_wqkvl[LLAY*QKVW*DD];
__device__ bf16 g_woh  [LLAY*DD*DD],   g_wol  [LLAY*DD*DD];
__device__ bf16 g_wfch [LLAY*FF*DD],   g_wfcl [LLAY*FF*DD];
__device__ bf16 g_wprh [LLAY*DD*FF],   g_wprl [LLAY*DD*FF];
__device__ bf16 g_lmh  [(size_t)VV*DD], g_lml [(size_t)VV*DD];

// ------------------------------------------------------------------
// helpers
// ------------------------------------------------------------------
__device__ __forceinline__ float block_reduce_sum_256(float v, float* sh) {
    int tid = threadIdx.x;
    sh[tid] = v;
    __syncthreads();
    #pragma unroll
    for (int s = 128; s > 0; s >>= 1) {
        if (tid < s) sh[tid] += sh[tid + s];
        __syncthreads();
    }
    return sh[0];
}
__device__ __forceinline__ float warp_reduce_sum(float v) {
    #pragma unroll
    for (int o = 16; o > 0; o >>= 1) v += __shfl_xor_sync(0xffffffffu, v, o);
    return v;
}
__device__ __forceinline__ float warp_reduce_max(float v) {
    #pragma unroll
    for (int o = 16; o > 0; o >>= 1) v = fmaxf(v, __shfl_xor_sync(0xffffffffu, v, o));
    return v;
}

__device__ __forceinline__ void split_store4(float4 v, bf16* hi, bf16* lo) {
    bf162 h0, h1, l0, l1;
    h0.x = __float2bfloat16_rn(v.x); h0.y = __float2bfloat16_rn(v.y);
    h1.x = __float2bfloat16_rn(v.z); h1.y = __float2bfloat16_rn(v.w);
    l0.x = __float2bfloat16_rn(v.x - __bfloat162float(h0.x));
    l0.y = __float2bfloat16_rn(v.y - __bfloat162float(h0.y));
    l1.x = __float2bfloat16_rn(v.z - __bfloat162float(h1.x));
    l1.y = __float2bfloat16_rn(v.w - __bfloat162float(h1.y));
    *(bf162*)hi = h0; *(bf162*)(hi + 2) = h1;
    *(bf162*)lo = l0; *(bf162*)(lo + 2) = l1;
}
__device__ __forceinline__ void split_store1(float v, bf16* hi, bf16* lo) {
    bf16 h = __float2bfloat16_rn(v);
    *hi = h;
    *lo = __float2bfloat16_rn(v - __bfloat162float(h));
}

// ------------------------------------------------------------------
// generic fp32 -> bf16 hi/lo split
// ------------------------------------------------------------------
__global__ void split_kernel(const float* __restrict__ src,
                             bf16* __restrict__ hi, bf16* __restrict__ lo,
                             int n4) {
    int i = blockIdx.x * blockDim.x + threadIdx.x;
    if (i >= n4) return;
    float4 v = ((const float4*)src)[i];
    split_store4(v, hi + (size_t)i*4, lo + (size_t)i*4);
}

// pack Wq|Wk|Wv -> split planes
__global__ void pack_split_qkv(const float* __restrict__ Wq,
                               const float* __restrict__ Wk,
                               const float* __restrict__ Wv) {
    int i4 = blockIdx.x * blockDim.x + threadIdx.x;
    const int total4 = LLAY * QKVW * DD / 4;
    if (i4 >= total4) return;
    size_t e = (size_t)i4 * 4;
    int c   = (int)(e % DD);
    int r   = (int)((e / DD) % QKVW);
    int lyr = (int)(e / ((size_t)DD * QKVW));
    const float* srow;
    if (r < DD)            srow = Wq + (size_t)lyr*DD*DD  + (size_t)r*DD;
    else if (r < DD + 256) srow = Wk + (size_t)lyr*256*DD + (size_t)(r-DD)*DD;
    else                   srow = Wv + (size_t)lyr*256*DD + (size_t)(r-DD-256)*DD;
    float4 v = *(const float4*)(srow + c);
    split_store4(v, g_wqkvh + e, g_wqkvl + e);
}

// ------------------------------------------------------------------
// embedding + rmsnorm:  x = x0 = norm(wte[idx])
// ------------------------------------------------------------------
__global__ void embed_norm_kernel(const int* __restrict__ idx,
                                  const float* __restrict__ wte) {
    __shared__ float sh[256];
    int row = blockIdx.x, tid = threadIdx.x;
    int tok = idx[row];
    const float* wrow = wte + (size_t)tok * DD;
    float v[3]; float ss = 0.f;
    #pragma unroll
    for (int j = 0; j < 3; ++j) { v[j] = wrow[tid + j*256]; ss += v[j]*v[j]; }
    float tot = block_reduce_sum_256(ss, sh);
    float sc = rsqrtf(tot * (1.0f/DD) + 1e-6f);
    #pragma unroll
    for (int j = 0; j < 3; ++j) {
        float o = v[j] * sc;
        g_x [(size_t)row*DD + tid + j*256] = o;
        g_x0[(size_t)row*DD + tid + j*256] = o;
    }
}

// ------------------------------------------------------------------
// residual mix + rmsnorm; writes xn fp32 + bf16 hi/lo planes
// ------------------------------------------------------------------
__global__ void resid_norm_kernel(const float* __restrict__ rl,
                                  const float* __restrict__ xl,
                                  int li) {
    __shared__ float sh[256];
    int row = blockIdx.x, tid = threadIdx.x;
    float rs = 1.f, xs = 0.f;
    if (li >= 0) { rs = rl[li]; xs = xl[li]; }
    float v[3]; float ss = 0.f;
    #pragma unroll
    for (int j = 0; j < 3; ++j) {
        size_t i = (size_t)row*DD + tid + j*256;
        float val = g_x[i]*rs;
        if (li >= 0) val += g_x0[i]*xs;
        v[j] = val; ss += val*val;
    }
    float tot = block_reduce_sum_256(ss, sh);
    float sc = rsqrtf(tot * (1.0f/DD) + 1e-6f);
    #pragma unroll
    for (int j = 0; j < 3; ++j) {
        size_t i = (size_t)row*DD + tid + j*256;
        if (li >= 0) g_x[i] = v[j];
        float o = v[j]*sc;
        g_xn[i] = o;
        split_store1(o, &g_xnh[i], &g_xnl[i]);
    }
}

// ------------------------------------------------------------------
// bf16x3 tensor-core GEMM with pre-split operands + cp.async pipeline.
// C[M,N] (+)= A[M,K]*B[N,K]^T  via Ah*Bh + Ah*Bl + Al*Bh.
// 128x128 tile, BK=16, 2 stages, 256 threads (8 warps 2x4, warp 64x32).
// EPI: 0 store fp32, 1 accumulate fp32, 2 relu^2 -> split bf16 planes,
//      3 softcap 15*tanh(x/15)
// ------------------------------------------------------------------
#define MMA_BF16(d, a, b)                                                     \
    asm volatile("mma.sync.aligned.m16n8k16.row.col.f32.bf16.bf16.f32 "       \
                 "{%0,%1,%2,%3},{%4,%5,%6,%7},{%8,%9},{%0,%1,%2,%3};"         \
                 : "+f"(d[0]), "+f"(d[1]), "+f"(d[2]), "+f"(d[3])             \
                 : "r"(a[0]), "r"(a[1]), "r"(a[2]), "r"(a[3]),                \
                   "r"(b[0]), "r"(b[1]));

template<int EPI>
__global__ void __launch_bounds__(256)
gemm_p_kernel(const bf16* __restrict__ Ah, const bf16* __restrict__ Al,
              const bf16* __restrict__ Bh, const bf16* __restrict__ Bl,
              float* __restrict__ C, bf16* __restrict__ Ch, bf16* __restrict__ Cl,
              int M, int N, int K) {
    __shared__ bf16 s[2][4][128][24];   // stage, plane(Ah,Al,Bh,Bl), row, k : 48KB

    const int tid = threadIdx.x, lane = tid & 31, warp = tid >> 5;
    const int wm = warp & 1, wn = warp >> 1;
    const int bm = blockIdx.y * 128, bn = blockIdx.x * 128;
    const int fr = lane >> 2, fq = (lane & 3) << 1;

    const bf16* src0 = Ah + (size_t)(bm + (tid >> 1))*K + ((tid & 1) << 3);
    const bf16* src1 = Al + (size_t)(bm + (tid >> 1))*K + ((tid & 1) << 3);
    const bf16* src2 = Bh + (size_t)(bn + (tid >> 1))*K + ((tid & 1) << 3);
    const bf16* src3 = Bl + (size_t)(bn + (tid >> 1))*K + ((tid & 1) << 3);
    const int lrow = tid >> 1, lch = (tid & 1) << 3;

    float acc[4][4][4];
    #pragma unroll
    for (int i = 0; i < 4; ++i)
        #pragma unroll
        for (int j = 0; j < 4; ++j)
            #pragma unroll
            for (int r = 0; r < 4; ++r) acc[i][j][r] = 0.f;

    const int nk = K >> 4;

    // prologue: load stage 0
    {
        uint32_t d0 = (uint32_t)__cvta_generic_to_shared(&s[0][0][lrow][lch]);
        uint32_t d1 = (uint32_t)__cvta_generic_to_shared(&s[0][1][lrow][lch]);
        uint32_t d2 = (uint32_t)__cvta_generic_to_shared(&s[0][2][lrow][lch]);
        uint32_t d3 = (uint32_t)__cvta_generic_to_shared(&s[0][3][lrow][lch]);
        asm volatile("cp.async.cg.shared.global [%0], [%1], 16;" :: "r"(d0), "l"(src0));
        asm volatile("cp.async.cg.shared.global [%0], [%1], 16;" :: "r"(d1), "l"(src1));
        asm volatile("cp.async.cg.shared.global [%0], [%1], 16;" :: "r"(d2), "l"(src2));
        asm volatile("cp.async.cg.shared.global [%0], [%1], 16;" :: "r"(d3), "l"(src3));
        asm volatile("cp.async.commit_group;");
    }

    for (int kt = 0; kt < nk; ++kt) {
        const int st = kt & 1;
        if (kt + 1 < nk) {
            int k0 = (kt + 1) << 4;
            int ns = st ^ 1;
            uint32_t d0 = (uint32_t)__cvta_generic_to_shared(&s[ns][0][lrow][lch]);
            uint32_t d1 = (uint32_t)__cvta_generic_to_shared(&s[ns][1][lrow][lch]);
            uint32_t d2 = (uint32_t)__cvta_generic_to_shared(&s[ns][2][lrow][lch]);
            uint32_t d3 = (uint32_t)__cvta_generic_to_shared(&s[ns][3][lrow][lch]);
            asm volatile("cp.async.cg.shared.global [%0], [%1], 16;" :: "r"(d0), "l"(src0 + k0));
            asm volatile("cp.async.cg.shared.global [%0], [%1], 16;" :: "r"(d1), "l"(src1 + k0));
            asm volatile("cp.async.cg.shared.global [%0], [%1], 16;" :: "r"(d2), "l"(src2 + k0));
            asm volatile("cp.async.cg.shared.global [%0], [%1], 16;" :: "r"(d3), "l"(src3 + k0));
            asm volatile("cp.async.commit_group;");
            asm volatile("cp.async.wait_group 1;");
        } else {
            asm volatile("cp.async.wait_group 0;");
        }
        __syncthreads();

        uint32_t ah[4][4], al[4][4], bh[4][2], bl[4][2];
        #pragma unroll
        for (int mi = 0; mi < 4; ++mi) {
            int r = wm*64 + mi*16 + fr;
            ah[mi][0] = *(const uint32_t*)&s[st][0][r  ][fq];
            ah[mi][1] = *(const uint32_t*)&s[st][0][r+8][fq];
            ah[mi][2] = *(const uint32_t*)&s[st][0][r  ][fq+8];
            ah[mi][3] = *(const uint32_t*)&s[st][0][r+8][fq+8];
            al[mi][0] = *(const uint32_t*)&s[st][1][r  ][fq];
            al[mi][1] = *(const uint32_t*)&s[st][1][r+8][fq];
            al[mi][2] = *(const uint32_t*)&s[st][1][r  ][fq+8];
            al[mi][3] = *(const uint32_t*)&s[st][1][r+8][fq+8];
        }
        #pragma unroll
        for (int ni = 0; ni < 4; ++ni) {
            int nr = wn*32 + ni*8 + fr;
            bh[ni][0] = *(const uint32_t*)&s[st][2][nr][fq];
            bh[ni][1] = *(const uint32_t*)&s[st][2][nr][fq+8];
            bl[ni][0] = *(const uint32_t*)&s[st][3][nr][fq];
            bl[ni][1] = *(const uint32_t*)&s[st][3][nr][fq+8];
        }
        #pragma unroll
        for (int mi = 0; mi < 4; ++mi)
            #pragma unroll
            for (int ni = 0; ni < 4; ++ni) {
                MMA_BF16(acc[mi][ni], ah[mi], bh[ni]);
                MMA_BF16(acc[mi][ni], ah[mi], bl[ni]);
                MMA_BF16(acc[mi][ni], al[mi], bh[ni]);
            }
        __syncthreads();
    }

    #pragma unroll
    for (int mi = 0; mi < 4; ++mi) {
        #pragma unroll
        for (int ni = 0; ni < 4; ++ni) {
            int row = bm + wm*64 + mi*16 + fr;
            int col = bn + wn*32 + ni*8 + fq;
            #pragma unroll
            for (int r = 0; r < 4; ++r) {
                int rr = row + (r >> 1)*8;
                int cc = col + (r & 1);
                float val = acc[mi][ni][r];
                size_t ix = (size_t)rr * N + cc;
                if (EPI == 1) {
                    C[ix] += val;
                } else if (EPI == 2) {
                    float re = fmaxf(val, 0.f);
                    split_store1(re * re, &Ch[ix], &Cl[ix]);
                } else if (EPI == 3) {
                    C[ix] = 15.0f * tanhf(val * (1.0f/15.0f));
                } else {
                    C[ix] = val;
                }
            }
        }
    }
}

// ------------------------------------------------------------------
// value-embedding gate
// ------------------------------------------------------------------
__global__ void ve_kernel(const int* __restrict__ idx,
                          const float* __restrict__ ve_table,
                          const float* __restrict__ gate_w) {
    __shared__ float gates[KVHH];
    int row = blockIdx.x, tid = threadIdx.x;
    if (tid < KVHH*32) {
        int g = tid >> 5, lane = tid & 31;
        float p = g_xn[(size_t)row*DD + lane] * gate_w[g*32 + lane];
        p = warp_reduce_sum(p);
        if (lane == 0) gates[g] = 2.0f / (1.0f + expf(-p));
    }
    __syncthreads();
    int tok = idx[row];
    g_qkv[(size_t)row*QKVW + 1024 + tid] += gates[tid >> 6] *
        ve_table[(size_t)tok*256 + tid];
}

// ------------------------------------------------------------------
// RoPE + per-head rmsnorm.  One warp per (row, head).
// ------------------------------------------------------------------
__global__ void rope_norm_kernel(float* __restrict__ p, int nh, int off) {
    int gw   = (blockIdx.x * blockDim.x + threadIdx.x) >> 5;
    int lane = threadIdx.x & 31;
    int row  = gw / nh;
    int head = gw - row*nh;
    int t    = row & (TT-1);
    float* base = p + (size_t)row*QKVW + off + head*HDD;
    float a = base[lane];
    float b = base[lane + 32];
    float inv = 1.0f / powf(10000.0f, (float)lane * (1.0f/32.0f));
    float ang = (float)t * inv;
    float s, c;
    sincosf(ang, &s, &c);
    float na =  a*c + b*s;
    float nb = -a*s + b*c;
    float ss = warp_reduce_sum(na*na + nb*nb);
    float sc = rsqrtf(ss * (1.0f/HDD) + 1e-6f);
    base[lane]      = na * sc;
    base[lane + 32] = nb * sc;
}

// ------------------------------------------------------------------
// tiled attention: block per (b, kvh, 32-query tile); 8 warps, each warp
// owns 4 queries x 3 heads.  K/V staged in smem, 3 heads share K reads.
// Writes y as bf16 hi/lo planes.
// ------------------------------------------------------------------
#define QT 32
__global__ void __launch_bounds__(256) attn_kernel(int w) {
    __shared__ float sq[QT*3][64];
    __shared__ float sk[32][68];
    __shared__ float sv[32][68];

    int tid = threadIdx.x, lane = tid & 31, warp = tid >> 5;
    int blk = blockIdx.x;
    int qt = blk & 31;
    int g  = (blk >> 5) & 3;
    int b  = blk >> 7;
    int q0 = qt * QT;

    for (int it = tid; it < 96*16; it += 256) {
        int qh = it >> 4, ds = (it & 15) << 2;
        int q = qh / 3, hl = qh % 3;
        const float* qp = g_qkv + (size_t)(b*TT + q0 + q)*QKVW + (g*3 + hl)*HDD + ds;
        *(float4*)&sq[qh][ds] = *(const float4*)qp;
    }

    float m[12], l[12], a0[12], a1[12];
    #pragma unroll
    for (int p = 0; p < 12; ++p) { m[p] = -1e30f; l[p] = 0.f; a0[p] = 0.f; a1[p] = 0.f; }

    int jlo = q0 - w + 1; if (jlo < 0) jlo = 0;
    int js0 = jlo & ~31;
    __syncthreads();

    for (int js = js0; js < q0 + QT; js += 32) {
        for (int it = tid; it < 512; it += 256) {
            int key = it >> 4, ds = (it & 15) << 2;
            const float* kp = g_qkv + (size_t)(b*TT + js + key)*QKVW + DD + g*HDD + ds;
            *(float4*)&sk[key][ds] = *(const float4*)kp;
            *(float4*)&sv[key][ds] = *(const float4*)(kp + 256);
        }
        __syncthreads();

        #pragma unroll
        for (int qi = 0; qi < 4; ++qi) {
            int qq = warp*4 + qi;
            int t  = q0 + qq;
            int j  = js + lane;
            bool valid = (j <= t) && (t - j < w);
            float s0 = -1e30f, s1 = -1e30f, s2 = -1e30f;
            if (valid) {
                float d0 = 0.f, d1 = 0.f, d2 = 0.f;
                #pragma unroll
                for (int ds = 0; ds < 64; ds += 4) {
                    float4 kv = *(const float4*)&sk[lane][ds];
                    float4 qa = *(const float4*)&sq[qq*3+0][ds];
                    float4 qb = *(const float4*)&sq[qq*3+1][ds];
                    float4 qc = *(const float4*)&sq[qq*3+2][ds];
                    d0 += qa.x*kv.x + qa.y*kv.y + qa.z*kv.z + qa.w*kv.w;
                    d1 += qb.x*kv.x + qb.y*kv.y + qb.z*kv.z + qb.w*kv.w;
                    d2 += qc.x*kv.x + qc.y*kv.y + qc.z*kv.z + qc.w*kv.w;
                }
                s0 = d0*0.125f; s1 = d1*0.125f; s2 = d2*0.125f;
            }
            float pr0, pr1, pr2;
            #pragma unroll
            for (int hl = 0; hl < 3; ++hl) {
                int p = qi*3 + hl;
                float sc = (hl == 0) ? s0 : (hl == 1) ? s1 : s2;
                float cm = warp_reduce_max(sc);
                float nm = fmaxf(m[p], cm);
                float pr = valid ? __expf(sc - nm) : 0.f;
                float corr = __expf(m[p] - nm);
                float sl = warp_reduce_sum(pr);
                l[p]  = l[p]*corr + sl;
                a0[p] *= corr; a1[p] *= corr;
                m[p] = nm;
                if (hl == 0) pr0 = pr; else if (hl == 1) pr1 = pr; else pr2 = pr;
            }
            #pragma unroll 8
            for (int kk = 0; kk < 32; ++kk) {
                float v0 = sv[kk][lane], v1 = sv[kk][lane+32];
                float pa = __shfl_sync(0xffffffffu, pr0, kk);
                float pb = __shfl_sync(0xffffffffu, pr1, kk);
                float pc = __shfl_sync(0xffffffffu, pr2, kk);
                a0[qi*3+0] = fmaf(pa, v0, a0[qi*3+0]);
                a1[qi*3+0] = fmaf(pa, v1, a1[qi*3+0]);
                a0[qi*3+1] = fmaf(pb, v0, a0[qi*3+1]);
                a1[qi*3+1] = fmaf(pb, v1, a1[qi*3+1]);
                a0[qi*3+2] = fmaf(pc, v0, a0[qi*3+2]);
                a1[qi*3+2] = fmaf(pc, v1, a1[qi*3+2]);
            }
        }
        __syncthreads();
    }

    #pragma unroll
    for (int qi = 0; qi < 4; ++qi) {
        #pragma unroll
        for (int hl = 0; hl < 3; ++hl) {
            int p = qi*3 + hl;
            size_t off = (size_t)(b*TT + q0 + warp*4 + qi)*DD + (g*3 + hl)*HDD;
            float inv = 1.0f / l[p];
            split_store1(a0[p]*inv, &g_yh[off + lane],      &g_yl[off + lane]);
            split_store1(a1[p]*inv, &g_yh[off + lane + 32], &g_yl[off + lane + 32]);
        }
    }
}

// ------------------------------------------------------------------
// host launcher
// ------------------------------------------------------------------
extern "C" void kernel_launch(void* const* d_in, const int* in_sizes, int n_in,
                              void* d_out, int out_size) {
    (void)in_sizes; (void)n_in; (void)out_size;
    const int*   idx    = (const int*)  d_in[0];
    const float* wte    = (const float*)d_in[1];
    const float* Wq     = (const float*)d_in[2];
    const float* Wk     = (const float*)d_in[3];
    const float* Wv     = (const float*)d_in[4];
    const float* Wo     = (const float*)d_in[5];
    const float* Wfc    = (const float*)d_in[6];
    const float* Wproj  = (const float*)d_in[7];
    const float* vetab  = (const float*)d_in[8];
    const float* vegate = (const float*)d_in[9];
    const float* rl     = (const float*)d_in[10];
    const float* xl     = (const float*)d_in[11];
    const float* lm     = (const float*)d_in[12];
    float* out = (float*)d_out;

    float *px, *pqkv;
    bf16 *pxnh, *pxnl, *pyh, *pyl, *phh, *phl;
    bf16 *pwqkvh, *pwqkvl, *pwoh, *pwol, *pwfch, *pwfcl, *pwprh, *pwprl, *plmh, *plml;
    cudaGetSymbolAddress((void**)&px,    g_x);
    cudaGetSymbolAddress((void**)&pqkv,  g_qkv);
    cudaGetSymbolAddress((void**)&pxnh,  g_xnh);
    cudaGetSymbolAddress((void**)&pxnl,  g_xnl);
    cudaGetSymbolAddress((void**)&pyh,   g_yh);
    cudaGetSymbolAddress((void**)&pyl,   g_yl);
    cudaGetSymbolAddress((void**)&phh,   g_hh);
    cudaGetSymbolAddress((void**)&phl,   g_hl);
    cudaGetSymbolAddress((void**)&pwqkvh,g_wqkvh);
    cudaGetSymbolAddress((void**)&pwqkvl,g_wqkvl);
    cudaGetSymbolAddress((void**)&pwoh,  g_woh);
    cudaGetSymbolAddress((void**)&pwol,  g_wol);
    cudaGetSymbolAddress((void**)&pwfch, g_wfch);
    cudaGetSymbolAddress((void**)&pwfcl, g_wfcl);
    cudaGetSymbolAddress((void**)&pwprh, g_wprh);
    cudaGetSymbolAddress((void**)&pwprl, g_wprl);
    cudaGetSymbolAddress((void**)&plmh,  g_lmh);
    cudaGetSymbolAddress((void**)&plml,  g_lml);

    const int windows[LLAY] = {TT/2, TT, TT/2, TT, TT/2, TT};
    bf16* nb = (bf16*)0;

    // one-time weight splits (every replay; deterministic)
    {
        int n4;
        n4 = LLAY*QKVW*DD/4;  pack_split_qkv<<<(n4+255)/256, 256>>>(Wq, Wk, Wv);
        n4 = LLAY*DD*DD/4;    split_kernel<<<(n4+255)/256, 256>>>(Wo,    pwoh,  pwol,  n4);
        n4 = LLAY*FF*DD/4;    split_kernel<<<(n4+255)/256, 256>>>(Wfc,   pwfch, pwfcl, n4);
        n4 = LLAY*DD*FF/4;    split_kernel<<<(n4+255)/256, 256>>>(Wproj, pwprh, pwprl, n4);
        n4 = VV*DD/4;         split_kernel<<<(n4+255)/256, 256>>>(lm,    plmh,  plml,  n4);
    }

    embed_norm_kernel<<<RR, 256>>>(idx, wte);

    for (int i = 0; i < LLAY; ++i) {
        resid_norm_kernel<<<RR, 256>>>(rl, xl, i);

        gemm_p_kernel<0><<<dim3(QKVW/128, RR/128), 256>>>(
            pxnh, pxnl, pwqkvh + (size_t)i*QKVW*DD, pwqkvl + (size_t)i*QKVW*DD,
            pqkv, nb, nb, RR, QKVW, DD);

        int slot = (i == 1) ? 0 : (i == 3) ? 1 : (i == 5) ? 2 : -1;
        if (slot >= 0)
            ve_kernel<<<RR, 256>>>(idx, vetab + (size_t)slot*VV*256,
                                   vegate + (size_t)slot*KVHH*32);

        rope_norm_kernel<<<(RR*HH)/8,   256>>>(pqkv, HH,   0);
        rope_norm_kernel<<<(RR*KVHH)/8, 256>>>(pqkv, KVHH, DD);

        attn_kernel<<<BB*KVHH*(TT/QT), 256>>>(windows[i]);

        gemm_p_kernel<1><<<dim3(DD/128, RR/128), 256>>>(
            pyh, pyl, pwoh + (size_t)i*DD*DD, pwol + (size_t)i*DD*DD,
            px, nb, nb, RR, DD, DD);

        resid_norm_kernel<<<RR, 256>>>(rl, xl, -1);

        gemm_p_kernel<2><<<dim3(FF/128, RR/128), 256>>>(
            pxnh, pxnl, pwfch + (size_t)i*FF*DD, pwfcl + (size_t)i*FF*DD,
            px, phh, phl, RR, FF, DD);

        gemm_p_kernel<1><<<dim3(DD/128, RR/128), 256>>>(
            phh, phl, pwprh + (size_t)i*DD*FF, pwprl + (size_t)i*DD*FF,
            px, nb, nb, RR, DD, FF);
    }

    resid_norm_kernel<<<RR, 256>>>(rl, xl, -1);
    gemm_p_kernel<3><<<dim3(VV/128, RR/128), 256>>>(
        pxnh, pxnl, plmh, plml, out, nb, nb, RR, VV, DD);
}

// round 5
// speedup vs baseline: 2.2197x; 1.0582x over previous
#include <cuda_runtime.h>
#include <cuda_bf16.h>
#include <math.h>
#include <stdint.h>

// ---- model constants ----
#define BB   2
#define TT   1024
#define RR   2048
#define DD   768
#define HH   12
#define KVHH 4
#define HDD  64
#define QKVW 1280
#define LLAY 6
#define VV   32000
#define FF   3072

typedef __nv_bfloat16 bf16;
typedef __nv_bfloat162 bf162;

// ---- scratch ----
__device__ float g_x  [RR*DD];
__device__ float g_x0 [RR*DD];
__device__ float g_xn [RR*DD];
__device__ float g_qkv[RR*QKVW];

__device__ bf16 g_xnh[RR*DD],  g_xnl[RR*DD];
__device__ bf16 g_yh [RR*DD],  g_yl [RR*DD];
__device__ bf16 g_hh [RR*FF],  g_hl [RR*FF];

__device__ bf16 g_wqkvh[LLAY*QKVW*DD], g_wqkvl[LLAY*QKVW*DD];
__device__ bf16 g_woh  [LLAY*DD*DD],   g_wol  [LLAY*DD*DD];
__device__ bf16 g_wfch [LLAY*FF*DD],   g_wfcl [LLAY*FF*DD];
__device__ bf16 g_wprh [LLAY*DD*FF],   g_wprl [LLAY*DD*FF];
__device__ bf16 g_lmh  [(size_t)VV*DD], g_lml [(size_t)VV*DD];

// ------------------------------------------------------------------
// helpers
// ------------------------------------------------------------------
__device__ __forceinline__ float block_reduce_sum_256(float v, float* sh) {
    int tid = threadIdx.x;
    sh[tid] = v;
    __syncthreads();
    #pragma unroll
    for (int s = 128; s > 0; s >>= 1) {
        if (tid < s) sh[tid] += sh[tid + s];
        __syncthreads();
    }
    return sh[0];
}
__device__ __forceinline__ float warp_reduce_sum(float v) {
    #pragma unroll
    for (int o = 16; o > 0; o >>= 1) v += __shfl_xor_sync(0xffffffffu, v, o);
    return v;
}
__device__ __forceinline__ float warp_reduce_max(float v) {
    #pragma unroll
    for (int o = 16; o > 0; o >>= 1) v = fmaxf(v, __shfl_xor_sync(0xffffffffu, v, o));
    return v;
}
__device__ __forceinline__ void split_store4(float4 v, bf16* hi, bf16* lo) {
    bf162 h0, h1, l0, l1;
    h0.x = __float2bfloat16_rn(v.x); h0.y = __float2bfloat16_rn(v.y);
    h1.x = __float2bfloat16_rn(v.z); h1.y = __float2bfloat16_rn(v.w);
    l0.x = __float2bfloat16_rn(v.x - __bfloat162float(h0.x));
    l0.y = __float2bfloat16_rn(v.y - __bfloat162float(h0.y));
    l1.x = __float2bfloat16_rn(v.z - __bfloat162float(h1.x));
    l1.y = __float2bfloat16_rn(v.w - __bfloat162float(h1.y));
    *(bf162*)hi = h0; *(bf162*)(hi + 2) = h1;
    *(bf162*)lo = l0; *(bf162*)(lo + 2) = l1;
}
__device__ __forceinline__ void split_store1(float v, bf16* hi, bf16* lo) {
    bf16 h = __float2bfloat16_rn(v);
    *hi = h;
    *lo = __float2bfloat16_rn(v - __bfloat162float(h));
}
__device__ __forceinline__ uint32_t smem_u32(const void* p) {
    uint32_t a;
    asm("{ .reg .u64 t; cvta.to.shared.u64 t, %1; cvt.u32.u64 %0, t; }" : "=r"(a) : "l"(p));
    return a;
}

// ------------------------------------------------------------------
// fp32 -> bf16 hi/lo split kernels
// ------------------------------------------------------------------
__global__ void split_kernel(const float* __restrict__ src,
                             bf16* __restrict__ hi, bf16* __restrict__ lo,
                             int n4) {
    int i = blockIdx.x * blockDim.x + threadIdx.x;
    if (i >= n4) return;
    float4 v = ((const float4*)src)[i];
    split_store4(v, hi + (size_t)i*4, lo + (size_t)i*4);
}
__global__ void pack_split_qkv(const float* __restrict__ Wq,
                               const float* __restrict__ Wk,
                               const float* __restrict__ Wv) {
    int i4 = blockIdx.x * blockDim.x + threadIdx.x;
    const int total4 = LLAY * QKVW * DD / 4;
    if (i4 >= total4) return;
    size_t e = (size_t)i4 * 4;
    int c   = (int)(e % DD);
    int r   = (int)((e / DD) % QKVW);
    int lyr = (int)(e / ((size_t)DD * QKVW));
    const float* srow;
    if (r < DD)            srow = Wq + (size_t)lyr*DD*DD  + (size_t)r*DD;
    else if (r < DD + 256) srow = Wk + (size_t)lyr*256*DD + (size_t)(r-DD)*DD;
    else                   srow = Wv + (size_t)lyr*256*DD + (size_t)(r-DD-256)*DD;
    float4 v = *(const float4*)(srow + c);
    split_store4(v, g_wqkvh + e, g_wqkvl + e);
}

// ------------------------------------------------------------------
// embedding + rmsnorm
// ------------------------------------------------------------------
__global__ void embed_norm_kernel(const int* __restrict__ idx,
                                  const float* __restrict__ wte) {
    __shared__ float sh[256];
    int row = blockIdx.x, tid = threadIdx.x;
    int tok = idx[row];
    const float* wrow = wte + (size_t)tok * DD;
    float v[3]; float ss = 0.f;
    #pragma unroll
    for (int j = 0; j < 3; ++j) { v[j] = wrow[tid + j*256]; ss += v[j]*v[j]; }
    float tot = block_reduce_sum_256(ss, sh);
    float sc = rsqrtf(tot * (1.0f/DD) + 1e-6f);
    #pragma unroll
    for (int j = 0; j < 3; ++j) {
        float o = v[j] * sc;
        g_x [(size_t)row*DD + tid + j*256] = o;
        g_x0[(size_t)row*DD + tid + j*256] = o;
    }
}

// ------------------------------------------------------------------
// residual mix + rmsnorm -> xn fp32 + bf16 hi/lo
// ------------------------------------------------------------------
__global__ void resid_norm_kernel(const float* __restrict__ rl,
                                  const float* __restrict__ xl,
                                  int li) {
    __shared__ float sh[256];
    int row = blockIdx.x, tid = threadIdx.x;
    float rs = 1.f, xs = 0.f;
    if (li >= 0) { rs = rl[li]; xs = xl[li]; }
    float v[3]; float ss = 0.f;
    #pragma unroll
    for (int j = 0; j < 3; ++j) {
        size_t i = (size_t)row*DD + tid + j*256;
        float val = g_x[i]*rs;
        if (li >= 0) val += g_x0[i]*xs;
        v[j] = val; ss += val*val;
    }
    float tot = block_reduce_sum_256(ss, sh);
    float sc = rsqrtf(tot * (1.0f/DD) + 1e-6f);
    #pragma unroll
    for (int j = 0; j < 3; ++j) {
        size_t i = (size_t)row*DD + tid + j*256;
        if (li >= 0) g_x[i] = v[j];
        float o = v[j]*sc;
        g_xn[i] = o;
        split_store1(o, &g_xnh[i], &g_xnl[i]);
    }
}

// ------------------------------------------------------------------
// bf16x3 mma.sync GEMM with ldmatrix + 3-stage cp.async pipeline.
// C[M,N] (+)= A[M,K]*B[N,K]^T  via Ah*Bh + Ah*Bl + Al*Bh.
// 128x128 tile, BK=32, 256 threads (8 warps 2x4, warp tile 64x32).
// smem: 3 stages x 4 planes x [128][40] bf16 (padded rows, conflict-free
// for both cp.async stores and ldmatrix 8-row sweeps).
// EPI: 0 store, 1 accumulate, 2 relu^2 -> bf16 hi/lo, 3 softcap tanh
// ------------------------------------------------------------------
#define PL_BYTES  10240               // 128*40*2
#define ST_BYTES  (4*PL_BYTES)        // 40960
#define GSMB      (3*ST_BYTES)        // 122880

#define MMA_BF16(d, a, b)                                                     \
    asm volatile("mma.sync.aligned.m16n8k16.row.col.f32.bf16.bf16.f32 "       \
                 "{%0,%1,%2,%3},{%4,%5,%6,%7},{%8,%9},{%0,%1,%2,%3};"         \
                 : "+f"(d[0]), "+f"(d[1]), "+f"(d[2]), "+f"(d[3])             \
                 : "r"(a[0]), "r"(a[1]), "r"(a[2]), "r"(a[3]),                \
                   "r"(b[0]), "r"(b[1]));

#define LDSM4(r0, r1, r2, r3, addr)                                           \
    asm volatile("ldmatrix.sync.aligned.m8n8.x4.shared.b16 {%0,%1,%2,%3},[%4];" \
                 : "=r"(r0), "=r"(r1), "=r"(r2), "=r"(r3) : "r"(addr));

template<int EPI>
__global__ void __launch_bounds__(256)
gemm_lm_kernel(const bf16* __restrict__ Ah, const bf16* __restrict__ Al,
               const bf16* __restrict__ Bh, const bf16* __restrict__ Bl,
               float* __restrict__ C, bf16* __restrict__ Ch, bf16* __restrict__ Cl,
               int M, int N, int K) {
    extern __shared__ char dsm[];
    const uint32_t tiles = smem_u32(dsm);

    const int tid = threadIdx.x, lane = tid & 31, warp = tid >> 5;
    const int wm = warp & 1, wn = warp >> 1;
    const int bm = blockIdx.y * 128, bn = blockIdx.x * 128;

    const bf16* Pp[4] = { Ah + (size_t)bm*K, Al + (size_t)bm*K,
                          Bh + (size_t)bn*K, Bl + (size_t)bn*K };

    float acc[4][4][4];
    #pragma unroll
    for (int i = 0; i < 4; ++i)
        #pragma unroll
        for (int j = 0; j < 4; ++j)
            #pragma unroll
            for (int r = 0; r < 4; ++r) acc[i][j][r] = 0.f;

    const int lrow = tid >> 2;          // 0..63
    const int lch  = tid & 3;           // chunk within row

    auto load_stage = [&](uint32_t sbase, int kt) {
        #pragma unroll
        for (int i = 0; i < 8; ++i) {
            const int pl  = i >> 1;
            const int row = ((i & 1) << 6) + lrow;
            const bf16* src = Pp[pl] + (size_t)row*K + kt*32 + lch*8;
            uint32_t dst = sbase + pl*PL_BYTES + row*80 + lch*16;
            asm volatile("cp.async.cg.shared.global [%0], [%1], 16;"
                         :: "r"(dst), "l"(src));
        }
        asm volatile("cp.async.commit_group;");
    };

    // ldmatrix address components (within a plane)
    const int arow = wm*64 + (lane & 15);
    const int acolx = (lane >> 4) << 3;            // 0 or 8
    const int brow = wn*32 + ((lane >> 4) << 3) + (lane & 7);
    const int bcolx = ((lane >> 3) & 1) << 3;      // 0 or 8

    auto compute = [&](uint32_t sbase) {
        #pragma unroll
        for (int kc = 0; kc < 32; kc += 16) {
            uint32_t ah[4][4], al[4][4], bh[4][2], bl[4][2];
            #pragma unroll
            for (int mi = 0; mi < 4; ++mi) {
                uint32_t aaddr = sbase + (arow + mi*16)*80 + (kc + acolx)*2;
                LDSM4(ah[mi][0], ah[mi][1], ah[mi][2], ah[mi][3], aaddr);
                LDSM4(al[mi][0], al[mi][1], al[mi][2], al[mi][3], aaddr + PL_BYTES);
            }
            #pragma unroll
            for (int nt = 0; nt < 2; ++nt) {
                uint32_t baddr = sbase + 2*PL_BYTES + (brow + nt*16)*80 + (kc + bcolx)*2;
                LDSM4(bh[nt*2][0], bh[nt*2][1], bh[nt*2+1][0], bh[nt*2+1][1], baddr);
                LDSM4(bl[nt*2][0], bl[nt*2][1], bl[nt*2+1][0], bl[nt*2+1][1], baddr + PL_BYTES);
            }
            #pragma unroll
            for (int mi = 0; mi < 4; ++mi)
                #pragma unroll
                for (int ni = 0; ni < 4; ++ni) {
                    MMA_BF16(acc[mi][ni], ah[mi], bh[ni]);
                    MMA_BF16(acc[mi][ni], ah[mi], bl[ni]);
                    MMA_BF16(acc[mi][ni], al[mi], bh[ni]);
                }
        }
    };

    const int nk = K >> 5;
    load_stage(tiles,            0);
    load_stage(tiles + ST_BYTES, 1);

    for (int kt = 0; kt < nk; ++kt) {
        uint32_t sb = tiles + (uint32_t)(kt % 3)*ST_BYTES;
        if (kt == nk - 1) { asm volatile("cp.async.wait_group 0;"); }
        else              { asm volatile("cp.async.wait_group 1;"); }
        __syncthreads();
        compute(sb);
        __syncthreads();
        if (kt + 2 < nk)
            load_stage(tiles + (uint32_t)((kt + 2) % 3)*ST_BYTES, kt + 2);
    }

    const int fr = lane >> 2, fq = (lane & 3) << 1;
    #pragma unroll
    for (int mi = 0; mi < 4; ++mi) {
        #pragma unroll
        for (int ni = 0; ni < 4; ++ni) {
            int row = bm + wm*64 + mi*16 + fr;
            int col = bn + wn*32 + ni*8 + fq;
            #pragma unroll
            for (int r = 0; r < 4; ++r) {
                int rr = row + (r >> 1)*8;
                int cc = col + (r & 1);
                float val = acc[mi][ni][r];
                size_t ix = (size_t)rr * N + cc;
                if (EPI == 1) {
                    C[ix] += val;
                } else if (EPI == 2) {
                    float re = fmaxf(val, 0.f);
                    split_store1(re * re, &Ch[ix], &Cl[ix]);
                } else if (EPI == 3) {
                    C[ix] = 15.0f * tanhf(val * (1.0f/15.0f));
                } else {
                    C[ix] = val;
                }
            }
        }
    }
}

// ------------------------------------------------------------------
// value-embedding gate
// ------------------------------------------------------------------
__global__ void ve_kernel(const int* __restrict__ idx,
                          const float* __restrict__ ve_table,
                          const float* __restrict__ gate_w) {
    __shared__ float gates[KVHH];
    int row = blockIdx.x, tid = threadIdx.x;
    if (tid < KVHH*32) {
        int g = tid >> 5, lane = tid & 31;
        float p = g_xn[(size_t)row*DD + lane] * gate_w[g*32 + lane];
        p = warp_reduce_sum(p);
        if (lane == 0) gates[g] = 2.0f / (1.0f + expf(-p));
    }
    __syncthreads();
    int tok = idx[row];
    g_qkv[(size_t)row*QKVW + 1024 + tid] += gates[tid >> 6] *
        ve_table[(size_t)tok*256 + tid];
}

// ------------------------------------------------------------------
// RoPE + per-head rmsnorm
// ------------------------------------------------------------------
__global__ void rope_norm_kernel(float* __restrict__ p, int nh, int off) {
    int gw   = (blockIdx.x * blockDim.x + threadIdx.x) >> 5;
    int lane = threadIdx.x & 31;
    int row  = gw / nh;
    int head = gw - row*nh;
    int t    = row & (TT-1);
    float* base = p + (size_t)row*QKVW + off + head*HDD;
    float a = base[lane];
    float b = base[lane + 32];
    float inv = 1.0f / powf(10000.0f, (float)lane * (1.0f/32.0f));
    float ang = (float)t * inv;
    float s, c;
    sincosf(ang, &s, &c);
    float na =  a*c + b*s;
    float nb = -a*s + b*c;
    float ss = warp_reduce_sum(na*na + nb*nb);
    float sc = rsqrtf(ss * (1.0f/HDD) + 1e-6f);
    base[lane]      = na * sc;
    base[lane + 32] = nb * sc;
}

// ------------------------------------------------------------------
// tiled attention
// ------------------------------------------------------------------
#define QT 32
__global__ void __launch_bounds__(256) attn_kernel(int w) {
    __shared__ float sq[QT*3][64];
    __shared__ float sk[32][68];
    __shared__ float sv[32][68];

    int tid = threadIdx.x, lane = tid & 31, warp = tid >> 5;
    int blk = blockIdx.x;
    int qt = blk & 31;
    int g  = (blk >> 5) & 3;
    int b  = blk >> 7;
    int q0 = qt * QT;

    for (int it = tid; it < 96*16; it += 256) {
        int qh = it >> 4, ds = (it & 15) << 2;
        int q = qh / 3, hl = qh % 3;
        const float* qp = g_qkv + (size_t)(b*TT + q0 + q)*QKVW + (g*3 + hl)*HDD + ds;
        *(float4*)&sq[qh][ds] = *(const float4*)qp;
    }

    float m[12], l[12], a0[12], a1[12];
    #pragma unroll
    for (int p = 0; p < 12; ++p) { m[p] = -1e30f; l[p] = 0.f; a0[p] = 0.f; a1[p] = 0.f; }

    int jlo = q0 - w + 1; if (jlo < 0) jlo = 0;
    int js0 = jlo & ~31;
    __syncthreads();

    for (int js = js0; js < q0 + QT; js += 32) {
        for (int it = tid; it < 512; it += 256) {
            int key = it >> 4, ds = (it & 15) << 2;
            const float* kp = g_qkv + (size_t)(b*TT + js + key)*QKVW + DD + g*HDD + ds;
            *(float4*)&sk[key][ds] = *(const float4*)kp;
            *(float4*)&sv[key][ds] = *(const float4*)(kp + 256);
        }
        __syncthreads();

        #pragma unroll
        for (int qi = 0; qi < 4; ++qi) {
            int qq = warp*4 + qi;
            int t  = q0 + qq;
            int j  = js + lane;
            bool valid = (j <= t) && (t - j < w);
            float s0 = -1e30f, s1 = -1e30f, s2 = -1e30f;
            if (valid) {
                float d0 = 0.f, d1 = 0.f, d2 = 0.f;
                #pragma unroll
                for (int ds = 0; ds < 64; ds += 4) {
                    float4 kv = *(const float4*)&sk[lane][ds];
                    float4 qa = *(const float4*)&sq[qq*3+0][ds];
                    float4 qb = *(const float4*)&sq[qq*3+1][ds];
                    float4 qc = *(const float4*)&sq[qq*3+2][ds];
                    d0 += qa.x*kv.x + qa.y*kv.y + qa.z*kv.z + qa.w*kv.w;
                    d1 += qb.x*kv.x + qb.y*kv.y + qb.z*kv.z + qb.w*kv.w;
                    d2 += qc.x*kv.x + qc.y*kv.y + qc.z*kv.z + qc.w*kv.w;
                }
                s0 = d0*0.125f; s1 = d1*0.125f; s2 = d2*0.125f;
            }
            float pr0, pr1, pr2;
            #pragma unroll
            for (int hl = 0; hl < 3; ++hl) {
                int p = qi*3 + hl;
                float sc = (hl == 0) ? s0 : (hl == 1) ? s1 : s2;
                float cm = warp_reduce_max(sc);
                float nm = fmaxf(m[p], cm);
                float pr = valid ? __expf(sc - nm) : 0.f;
                float corr = __expf(m[p] - nm);
                float sl = warp_reduce_sum(pr);
                l[p]  = l[p]*corr + sl;
                a0[p] *= corr; a1[p] *= corr;
                m[p] = nm;
                if (hl == 0) pr0 = pr; else if (hl == 1) pr1 = pr; else pr2 = pr;
            }
            #pragma unroll 8
            for (int kk = 0; kk < 32; ++kk) {
                float v0 = sv[kk][lane], v1 = sv[kk][lane+32];
                float pa = __shfl_sync(0xffffffffu, pr0, kk);
                float pb = __shfl_sync(0xffffffffu, pr1, kk);
                float pc = __shfl_sync(0xffffffffu, pr2, kk);
                a0[qi*3+0] = fmaf(pa, v0, a0[qi*3+0]);
                a1[qi*3+0] = fmaf(pa, v1, a1[qi*3+0]);
                a0[qi*3+1] = fmaf(pb, v0, a0[qi*3+1]);
                a1[qi*3+1] = fmaf(pb, v1, a1[qi*3+1]);
                a0[qi*3+2] = fmaf(pc, v0, a0[qi*3+2]);
                a1[qi*3+2] = fmaf(pc, v1, a1[qi*3+2]);
            }
        }
        __syncthreads();
    }

    #pragma unroll
    for (int qi = 0; qi < 4; ++qi) {
        #pragma unroll
        for (int hl = 0; hl < 3; ++hl) {
            int p = qi*3 + hl;
            size_t off = (size_t)(b*TT + q0 + warp*4 + qi)*DD + (g*3 + hl)*HDD;
            float inv = 1.0f / l[p];
            split_store1(a0[p]*inv, &g_yh[off + lane],      &g_yl[off + lane]);
            split_store1(a1[p]*inv, &g_yh[off + lane + 32], &g_yl[off + lane + 32]);
        }
    }
}

// ------------------------------------------------------------------
// host launcher
// ------------------------------------------------------------------
extern "C" void kernel_launch(void* const* d_in, const int* in_sizes, int n_in,
                              void* d_out, int out_size) {
    (void)in_sizes; (void)n_in; (void)out_size;
    const int*   idx    = (const int*)  d_in[0];
    const float* wte    = (const float*)d_in[1];
    const float* Wq     = (const float*)d_in[2];
    const float* Wk     = (const float*)d_in[3];
    const float* Wv     = (const float*)d_in[4];
    const float* Wo     = (const float*)d_in[5];
    const float* Wfc    = (const float*)d_in[6];
    const float* Wproj  = (const float*)d_in[7];
    const float* vetab  = (const float*)d_in[8];
    const float* vegate = (const float*)d_in[9];
    const float* rl     = (const float*)d_in[10];
    const float* xl     = (const float*)d_in[11];
    const float* lm     = (const float*)d_in[12];
    float* out = (float*)d_out;

    float *px, *pqkv;
    bf16 *pxnh, *pxnl, *pyh, *pyl, *phh, *phl;
    bf16 *pwqkvh, *pwqkvl, *pwoh, *pwol, *pwfch, *pwfcl, *pwprh, *pwprl, *plmh, *plml;
    cudaGetSymbolAddress((void**)&px,    g_x);
    cudaGetSymbolAddress((void**)&pqkv,  g_qkv);
    cudaGetSymbolAddress((void**)&pxnh,  g_xnh);
    cudaGetSymbolAddress((void**)&pxnl,  g_xnl);
    cudaGetSymbolAddress((void**)&pyh,   g_yh);
    cudaGetSymbolAddress((void**)&pyl,   g_yl);
    cudaGetSymbolAddress((void**)&phh,   g_hh);
    cudaGetSymbolAddress((void**)&phl,   g_hl);
    cudaGetSymbolAddress((void**)&pwqkvh,g_wqkvh);
    cudaGetSymbolAddress((void**)&pwqkvl,g_wqkvl);
    cudaGetSymbolAddress((void**)&pwoh,  g_woh);
    cudaGetSymbolAddress((void**)&pwol,  g_wol);
    cudaGetSymbolAddress((void**)&pwfch, g_wfch);
    cudaGetSymbolAddress((void**)&pwfcl, g_wfcl);
    cudaGetSymbolAddress((void**)&pwprh, g_wprh);
    cudaGetSymbolAddress((void**)&pwprl, g_wprl);
    cudaGetSymbolAddress((void**)&plmh,  g_lmh);
    cudaGetSymbolAddress((void**)&plml,  g_lml);

    cudaFuncSetAttribute(gemm_lm_kernel<0>, cudaFuncAttributeMaxDynamicSharedMemorySize, GSMB);
    cudaFuncSetAttribute(gemm_lm_kernel<1>, cudaFuncAttributeMaxDynamicSharedMemorySize, GSMB);
    cudaFuncSetAttribute(gemm_lm_kernel<2>, cudaFuncAttributeMaxDynamicSharedMemorySize, GSMB);
    cudaFuncSetAttribute(gemm_lm_kernel<3>, cudaFuncAttributeMaxDynamicSharedMemorySize, GSMB);

    const int windows[LLAY] = {TT/2, TT, TT/2, TT, TT/2, TT};
    bf16* nb = (bf16*)0;
    int n4;

    // launches 1-3, then the profiled QKV GEMM at launch 4
    n4 = LLAY*QKVW*DD/4;  pack_split_qkv<<<(n4+255)/256, 256>>>(Wq, Wk, Wv);     // 1
    embed_norm_kernel<<<RR, 256>>>(idx, wte);                                    // 2
    resid_norm_kernel<<<RR, 256>>>(rl, xl, 0);                                   // 3
    gemm_lm_kernel<0><<<dim3(QKVW/128, RR/128), 256, GSMB>>>(                    // 4
        pxnh, pxnl, pwqkvh, pwqkvl, pqkv, nb, nb, RR, QKVW, DD);

    // remaining weight splits
    n4 = LLAY*DD*DD/4;    split_kernel<<<(n4+255)/256, 256>>>(Wo,    pwoh,  pwol,  n4);
    n4 = LLAY*FF*DD/4;    split_kernel<<<(n4+255)/256, 256>>>(Wfc,   pwfch, pwfcl, n4);
    n4 = LLAY*DD*FF/4;    split_kernel<<<(n4+255)/256, 256>>>(Wproj, pwprh, pwprl, n4);
    n4 = VV*DD/4;         split_kernel<<<(n4+255)/256, 256>>>(lm,    plmh,  plml,  n4);

    for (int i = 0; i < LLAY; ++i) {
        if (i > 0) {
            resid_norm_kernel<<<RR, 256>>>(rl, xl, i);
            gemm_lm_kernel<0><<<dim3(QKVW/128, RR/128), 256, GSMB>>>(
                pxnh, pxnl, pwqkvh + (size_t)i*QKVW*DD, pwqkvl + (size_t)i*QKVW*DD,
                pqkv, nb, nb, RR, QKVW, DD);
        }

        int slot = (i == 1) ? 0 : (i == 3) ? 1 : (i == 5) ? 2 : -1;
        if (slot >= 0)
            ve_kernel<<<RR, 256>>>(idx, vetab + (size_t)slot*VV*256,
                                   vegate + (size_t)slot*KVHH*32);

        rope_norm_kernel<<<(RR*HH)/8,   256>>>(pqkv, HH,   0);
        rope_norm_kernel<<<(RR*KVHH)/8, 256>>>(pqkv, KVHH, DD);

        attn_kernel<<<BB*KVHH*(TT/QT), 256>>>(windows[i]);

        gemm_lm_kernel<1><<<dim3(DD/128, RR/128), 256, GSMB>>>(
            pyh, pyl, pwoh + (size_t)i*DD*DD, pwol + (size_t)i*DD*DD,
            px, nb, nb, RR, DD, DD);

        resid_norm_kernel<<<RR, 256>>>(rl, xl, -1);

        gemm_lm_kernel<2><<<dim3(FF/128, RR/128), 256, GSMB>>>(
            pxnh, pxnl, pwfch + (size_t)i*FF*DD, pwfcl + (size_t)i*FF*DD,
            px, phh, phl, RR, FF, DD);

        gemm_lm_kernel<1><<<dim3(DD/128, RR/128), 256, GSMB>>>(
            phh, phl, pwprh + (size_t)i*DD*FF, pwprl + (size_t)i*DD*FF,
            px, nb, nb, RR, DD, FF);
    }

    resid_norm_kernel<<<RR, 256>>>(rl, xl, -1);
    gemm_lm_kernel<3><<<dim3(VV/128, RR/128), 256, GSMB>>>(
        pxnh, pxnl, plmh, plml, out, nb, nb, RR, VV, DD);
}

// round 6
// speedup vs baseline: 2.4138x; 1.0875x over previous
#include <cuda_runtime.h>
#include <cuda_bf16.h>
#include <math.h>
#include <stdint.h>

// ---- model constants ----
#define BB   2
#define TT   1024
#define RR   2048
#define DD   768
#define HH   12
#define KVHH 4
#define HDD  64
#define QKVW 1280
#define LLAY 6
#define VV   32000
#define FF   3072

typedef __nv_bfloat16 bf16;
typedef __nv_bfloat162 bf162;

// ---- scratch ----
__device__ float g_x  [RR*DD];
__device__ float g_x0 [RR*DD];
__device__ float g_xn [RR*DD];
__device__ float g_qkv[RR*QKVW];

__device__ bf16 g_xnh[RR*DD],  g_xnl[RR*DD];
__device__ bf16 g_yh [RR*DD],  g_yl [RR*DD];
__device__ bf16 g_hh [RR*FF],  g_hl [RR*FF];

__device__ bf16 g_wqkvh[LLAY*QKVW*DD], g_wqkvl[LLAY*QKVW*DD];
__device__ bf16 g_woh  [LLAY*DD*DD],   g_wol  [LLAY*DD*DD];
__device__ bf16 g_wfch [LLAY*FF*DD],   g_wfcl [LLAY*FF*DD];
__device__ bf16 g_wprh [LLAY*DD*FF],   g_wprl [LLAY*DD*FF];
__device__ bf16 g_lmh  [(size_t)VV*DD], g_lml [(size_t)VV*DD];

// ------------------------------------------------------------------
// helpers
// ------------------------------------------------------------------
__device__ __forceinline__ float block_reduce_sum_256(float v, float* sh) {
    int tid = threadIdx.x;
    sh[tid] = v;
    __syncthreads();
    #pragma unroll
    for (int s = 128; s > 0; s >>= 1) {
        if (tid < s) sh[tid] += sh[tid + s];
        __syncthreads();
    }
    return sh[0];
}
__device__ __forceinline__ float warp_reduce_sum(float v) {
    #pragma unroll
    for (int o = 16; o > 0; o >>= 1) v += __shfl_xor_sync(0xffffffffu, v, o);
    return v;
}
__device__ __forceinline__ float warp_reduce_max(float v) {
    #pragma unroll
    for (int o = 16; o > 0; o >>= 1) v = fmaxf(v, __shfl_xor_sync(0xffffffffu, v, o));
    return v;
}
__device__ __forceinline__ void split_store4(float4 v, bf16* hi, bf16* lo) {
    bf162 h0, h1, l0, l1;
    h0.x = __float2bfloat16_rn(v.x); h0.y = __float2bfloat16_rn(v.y);
    h1.x = __float2bfloat16_rn(v.z); h1.y = __float2bfloat16_rn(v.w);
    l0.x = __float2bfloat16_rn(v.x - __bfloat162float(h0.x));
    l0.y = __float2bfloat16_rn(v.y - __bfloat162float(h0.y));
    l1.x = __float2bfloat16_rn(v.z - __bfloat162float(h1.x));
    l1.y = __float2bfloat16_rn(v.w - __bfloat162float(h1.y));
    *(bf162*)hi = h0; *(bf162*)(hi + 2) = h1;
    *(bf162*)lo = l0; *(bf162*)(lo + 2) = l1;
}
__device__ __forceinline__ void split_store1(float v, bf16* hi, bf16* lo) {
    bf16 h = __float2bfloat16_rn(v);
    *hi = h;
    *lo = __float2bfloat16_rn(v - __bfloat162float(h));
}
__device__ __forceinline__ uint32_t smem_u32(const void* p) {
    uint32_t a;
    asm("{ .reg .u64 t; cvta.to.shared.u64 t, %1; cvt.u32.u64 %0, t; }" : "=r"(a) : "l"(p));
    return a;
}

// ------------------------------------------------------------------
// fp32 -> bf16 hi/lo split kernels
// ------------------------------------------------------------------
__global__ void split_kernel(const float* __restrict__ src,
                             bf16* __restrict__ hi, bf16* __restrict__ lo,
                             int n4) {
    int i = blockIdx.x * blockDim.x + threadIdx.x;
    if (i >= n4) return;
    float4 v = ((const float4*)src)[i];
    split_store4(v, hi + (size_t)i*4, lo + (size_t)i*4);
}
__global__ void pack_split_qkv(const float* __restrict__ Wq,
                               const float* __restrict__ Wk,
                               const float* __restrict__ Wv) {
    int i4 = blockIdx.x * blockDim.x + threadIdx.x;
    const int total4 = LLAY * QKVW * DD / 4;
    if (i4 >= total4) return;
    size_t e = (size_t)i4 * 4;
    int c   = (int)(e % DD);
    int r   = (int)((e / DD) % QKVW);
    int lyr = (int)(e / ((size_t)DD * QKVW));
    const float* srow;
    if (r < DD)            srow = Wq + (size_t)lyr*DD*DD  + (size_t)r*DD;
    else if (r < DD + 256) srow = Wk + (size_t)lyr*256*DD + (size_t)(r-DD)*DD;
    else                   srow = Wv + (size_t)lyr*256*DD + (size_t)(r-DD-256)*DD;
    float4 v = *(const float4*)(srow + c);
    split_store4(v, g_wqkvh + e, g_wqkvl + e);
}

// ------------------------------------------------------------------
// embedding + rmsnorm
// ------------------------------------------------------------------
__global__ void embed_norm_kernel(const int* __restrict__ idx,
                                  const float* __restrict__ wte) {
    __shared__ float sh[256];
    int row = blockIdx.x, tid = threadIdx.x;
    int tok = idx[row];
    const float* wrow = wte + (size_t)tok * DD;
    float v[3]; float ss = 0.f;
    #pragma unroll
    for (int j = 0; j < 3; ++j) { v[j] = wrow[tid + j*256]; ss += v[j]*v[j]; }
    float tot = block_reduce_sum_256(ss, sh);
    float sc = rsqrtf(tot * (1.0f/DD) + 1e-6f);
    #pragma unroll
    for (int j = 0; j < 3; ++j) {
        float o = v[j] * sc;
        g_x [(size_t)row*DD + tid + j*256] = o;
        g_x0[(size_t)row*DD + tid + j*256] = o;
    }
}

// ------------------------------------------------------------------
// residual mix + rmsnorm -> xn fp32 + bf16 hi/lo
// ------------------------------------------------------------------
__global__ void resid_norm_kernel(const float* __restrict__ rl,
                                  const float* __restrict__ xl,
                                  int li) {
    __shared__ float sh[256];
    int row = blockIdx.x, tid = threadIdx.x;
    float rs = 1.f, xs = 0.f;
    if (li >= 0) { rs = rl[li]; xs = xl[li]; }
    float v[3]; float ss = 0.f;
    #pragma unroll
    for (int j = 0; j < 3; ++j) {
        size_t i = (size_t)row*DD + tid + j*256;
        float val = g_x[i]*rs;
        if (li >= 0) val += g_x0[i]*xs;
        v[j] = val; ss += val*val;
    }
    float tot = block_reduce_sum_256(ss, sh);
    float sc = rsqrtf(tot * (1.0f/DD) + 1e-6f);
    #pragma unroll
    for (int j = 0; j < 3; ++j) {
        size_t i = (size_t)row*DD + tid + j*256;
        if (li >= 0) g_x[i] = v[j];
        float o = v[j]*sc;
        g_xn[i] = o;
        split_store1(o, &g_xnh[i], &g_xnl[i]);
    }
}

// ------------------------------------------------------------------
// bf16x3 mma.sync GEMM: ldmatrix + 2-stage cp.async pipeline,
// 80KB smem -> 2 CTAs/SM (16 warps) for latency hiding.
// C[M,N] (+)= A[M,K]*B[N,K]^T  via Ah*Bh + Ah*Bl + Al*Bh.
// 128x128 tile, BK=32, 256 threads (8 warps 2x4, warp tile 64x32).
// EPI: 0 store, 1 accumulate, 2 relu^2 -> bf16 hi/lo, 3 softcap tanh
// ------------------------------------------------------------------
#define PL_BYTES  10240               // 128*40*2
#define ST_BYTES  (4*PL_BYTES)        // 40960
#define GSMB      (2*ST_BYTES)        // 81920

#define MMA_BF16(d, a, b)                                                     \
    asm volatile("mma.sync.aligned.m16n8k16.row.col.f32.bf16.bf16.f32 "       \
                 "{%0,%1,%2,%3},{%4,%5,%6,%7},{%8,%9},{%0,%1,%2,%3};"         \
                 : "+f"(d[0]), "+f"(d[1]), "+f"(d[2]), "+f"(d[3])             \
                 : "r"(a[0]), "r"(a[1]), "r"(a[2]), "r"(a[3]),                \
                   "r"(b[0]), "r"(b[1]));

#define LDSM4(r0, r1, r2, r3, addr)                                           \
    asm volatile("ldmatrix.sync.aligned.m8n8.x4.shared.b16 {%0,%1,%2,%3},[%4];" \
                 : "=r"(r0), "=r"(r1), "=r"(r2), "=r"(r3) : "r"(addr));

template<int EPI>
__global__ void __launch_bounds__(256, 2)
gemm_lm_kernel(const bf16* __restrict__ Ah, const bf16* __restrict__ Al,
               const bf16* __restrict__ Bh, const bf16* __restrict__ Bl,
               float* __restrict__ C, bf16* __restrict__ Ch, bf16* __restrict__ Cl,
               int M, int N, int K) {
    extern __shared__ char dsm[];
    const uint32_t tiles = smem_u32(dsm);

    const int tid = threadIdx.x, lane = tid & 31, warp = tid >> 5;
    const int wm = warp & 1, wn = warp >> 1;
    const int bm = blockIdx.y * 128, bn = blockIdx.x * 128;

    const bf16* Pp[4] = { Ah + (size_t)bm*K, Al + (size_t)bm*K,
                          Bh + (size_t)bn*K, Bl + (size_t)bn*K };

    float acc[4][4][4];
    #pragma unroll
    for (int i = 0; i < 4; ++i)
        #pragma unroll
        for (int j = 0; j < 4; ++j)
            #pragma unroll
            for (int r = 0; r < 4; ++r) acc[i][j][r] = 0.f;

    const int lrow = tid >> 2;          // 0..63
    const int lch  = tid & 3;           // chunk within row

    auto load_stage = [&](uint32_t sbase, int kt) {
        #pragma unroll
        for (int i = 0; i < 8; ++i) {
            const int pl  = i >> 1;
            const int row = ((i & 1) << 6) + lrow;
            const bf16* src = Pp[pl] + (size_t)row*K + kt*32 + lch*8;
            uint32_t dst = sbase + pl*PL_BYTES + row*80 + lch*16;
            asm volatile("cp.async.cg.shared.global [%0], [%1], 16;"
                         :: "r"(dst), "l"(src));
        }
        asm volatile("cp.async.commit_group;");
    };

    // ldmatrix address components (within a plane)
    const int arow = wm*64 + (lane & 15);
    const int acolx = (lane >> 4) << 3;            // 0 or 8
    const int brow = wn*32 + ((lane >> 4) << 3) + (lane & 7);
    const int bcolx = ((lane >> 3) & 1) << 3;      // 0 or 8

    auto compute = [&](uint32_t sbase) {
        #pragma unroll
        for (int kc = 0; kc < 32; kc += 16) {
            uint32_t ah[4][4], al[4][4], bh[4][2], bl[4][2];
            #pragma unroll
            for (int mi = 0; mi < 4; ++mi) {
                uint32_t aaddr = sbase + (arow + mi*16)*80 + (kc + acolx)*2;
                LDSM4(ah[mi][0], ah[mi][1], ah[mi][2], ah[mi][3], aaddr);
                LDSM4(al[mi][0], al[mi][1], al[mi][2], al[mi][3], aaddr + PL_BYTES);
            }
            #pragma unroll
            for (int nt = 0; nt < 2; ++nt) {
                uint32_t baddr = sbase + 2*PL_BYTES + (brow + nt*16)*80 + (kc + bcolx)*2;
                LDSM4(bh[nt*2][0], bh[nt*2][1], bh[nt*2+1][0], bh[nt*2+1][1], baddr);
                LDSM4(bl[nt*2][0], bl[nt*2][1], bl[nt*2+1][0], bl[nt*2+1][1], baddr + PL_BYTES);
            }
            #pragma unroll
            for (int mi = 0; mi < 4; ++mi)
                #pragma unroll
                for (int ni = 0; ni < 4; ++ni) {
                    MMA_BF16(acc[mi][ni], ah[mi], bh[ni]);
                    MMA_BF16(acc[mi][ni], ah[mi], bl[ni]);
                    MMA_BF16(acc[mi][ni], al[mi], bh[ni]);
                }
        }
    };

    const int nk = K >> 5;
    load_stage(tiles,            0);
    if (nk > 1) load_stage(tiles + ST_BYTES, 1);

    for (int kt = 0; kt < nk; ++kt) {
        uint32_t sb = tiles + (uint32_t)(kt & 1)*ST_BYTES;
        if (kt == nk - 1) { asm volatile("cp.async.wait_group 0;"); }
        else              { asm volatile("cp.async.wait_group 1;"); }
        __syncthreads();
        compute(sb);
        __syncthreads();
        if (kt + 2 < nk)
            load_stage(sb, kt + 2);
    }

    const int fr = lane >> 2, fq = (lane & 3) << 1;
    #pragma unroll
    for (int mi = 0; mi < 4; ++mi) {
        #pragma unroll
        for (int ni = 0; ni < 4; ++ni) {
            int row = bm + wm*64 + mi*16 + fr;
            int col = bn + wn*32 + ni*8 + fq;
            #pragma unroll
            for (int r = 0; r < 4; ++r) {
                int rr = row + (r >> 1)*8;
                int cc = col + (r & 1);
                float val = acc[mi][ni][r];
                size_t ix = (size_t)rr * N + cc;
                if (EPI == 1) {
                    C[ix] += val;
                } else if (EPI == 2) {
                    float re = fmaxf(val, 0.f);
                    split_store1(re * re, &Ch[ix], &Cl[ix]);
                } else if (EPI == 3) {
                    C[ix] = 15.0f * tanhf(val * (1.0f/15.0f));
                } else {
                    C[ix] = val;
                }
            }
        }
    }
}

// ------------------------------------------------------------------
// value-embedding gate
// ------------------------------------------------------------------
__global__ void ve_kernel(const int* __restrict__ idx,
                          const float* __restrict__ ve_table,
                          const float* __restrict__ gate_w) {
    __shared__ float gates[KVHH];
    int row = blockIdx.x, tid = threadIdx.x;
    if (tid < KVHH*32) {
        int g = tid >> 5, lane = tid & 31;
        float p = g_xn[(size_t)row*DD + lane] * gate_w[g*32 + lane];
        p = warp_reduce_sum(p);
        if (lane == 0) gates[g] = 2.0f / (1.0f + expf(-p));
    }
    __syncthreads();
    int tok = idx[row];
    g_qkv[(size_t)row*QKVW + 1024 + tid] += gates[tid >> 6] *
        ve_table[(size_t)tok*256 + tid];
}

// ------------------------------------------------------------------
// RoPE + per-head rmsnorm
// ------------------------------------------------------------------
__global__ void rope_norm_kernel(float* __restrict__ p, int nh, int off) {
    int gw   = (blockIdx.x * blockDim.x + threadIdx.x) >> 5;
    int lane = threadIdx.x & 31;
    int row  = gw / nh;
    int head = gw - row*nh;
    int t    = row & (TT-1);
    float* base = p + (size_t)row*QKVW + off + head*HDD;
    float a = base[lane];
    float b = base[lane + 32];
    float inv = 1.0f / powf(10000.0f, (float)lane * (1.0f/32.0f));
    float ang = (float)t * inv;
    float s, c;
    sincosf(ang, &s, &c);
    float na =  a*c + b*s;
    float nb = -a*s + b*c;
    float ss = warp_reduce_sum(na*na + nb*nb);
    float sc = rsqrtf(ss * (1.0f/HDD) + 1e-6f);
    base[lane]      = na * sc;
    base[lane + 32] = nb * sc;
}

// ------------------------------------------------------------------
// tiled attention
// ------------------------------------------------------------------
#define QT 32
__global__ void __launch_bounds__(256) attn_kernel(int w) {
    __shared__ float sq[QT*3][64];
    __shared__ float sk[32][68];
    __shared__ float sv[32][68];

    int tid = threadIdx.x, lane = tid & 31, warp = tid >> 5;
    int blk = blockIdx.x;
    int qt = blk & 31;
    int g  = (blk >> 5) & 3;
    int b  = blk >> 7;
    int q0 = qt * QT;

    for (int it = tid; it < 96*16; it += 256) {
        int qh = it >> 4, ds = (it & 15) << 2;
        int q = qh / 3, hl = qh % 3;
        const float* qp = g_qkv + (size_t)(b*TT + q0 + q)*QKVW + (g*3 + hl)*HDD + ds;
        *(float4*)&sq[qh][ds] = *(const float4*)qp;
    }

    float m[12], l[12], a0[12], a1[12];
    #pragma unroll
    for (int p = 0; p < 12; ++p) { m[p] = -1e30f; l[p] = 0.f; a0[p] = 0.f; a1[p] = 0.f; }

    int jlo = q0 - w + 1; if (jlo < 0) jlo = 0;
    int js0 = jlo & ~31;
    __syncthreads();

    for (int js = js0; js < q0 + QT; js += 32) {
        for (int it = tid; it < 512; it += 256) {
            int key = it >> 4, ds = (it & 15) << 2;
            const float* kp = g_qkv + (size_t)(b*TT + js + key)*QKVW + DD + g*HDD + ds;
            *(float4*)&sk[key][ds] = *(const float4*)kp;
            *(float4*)&sv[key][ds] = *(const float4*)(kp + 256);
        }
        __syncthreads();

        #pragma unroll
        for (int qi = 0; qi < 4; ++qi) {
            int qq = warp*4 + qi;
            int t  = q0 + qq;
            int j  = js + lane;
            bool valid = (j <= t) && (t - j < w);
            float s0 = -1e30f, s1 = -1e30f, s2 = -1e30f;
            if (valid) {
                float d0 = 0.f, d1 = 0.f, d2 = 0.f;
                #pragma unroll
                for (int ds = 0; ds < 64; ds += 4) {
                    float4 kv = *(const float4*)&sk[lane][ds];
                    float4 qa = *(const float4*)&sq[qq*3+0][ds];
                    float4 qb = *(const float4*)&sq[qq*3+1][ds];
                    float4 qc = *(const float4*)&sq[qq*3+2][ds];
                    d0 += qa.x*kv.x + qa.y*kv.y + qa.z*kv.z + qa.w*kv.w;
                    d1 += qb.x*kv.x + qb.y*kv.y + qb.z*kv.z + qb.w*kv.w;
                    d2 += qc.x*kv.x + qc.y*kv.y + qc.z*kv.z + qc.w*kv.w;
                }
                s0 = d0*0.125f; s1 = d1*0.125f; s2 = d2*0.125f;
            }
            float pr0, pr1, pr2;
            #pragma unroll
            for (int hl = 0; hl < 3; ++hl) {
                int p = qi*3 + hl;
                float sc = (hl == 0) ? s0 : (hl == 1) ? s1 : s2;
                float cm = warp_reduce_max(sc);
                float nm = fmaxf(m[p], cm);
                float pr = valid ? __expf(sc - nm) : 0.f;
                float corr = __expf(m[p] - nm);
                float sl = warp_reduce_sum(pr);
                l[p]  = l[p]*corr + sl;
                a0[p] *= corr; a1[p] *= corr;
                m[p] = nm;
                if (hl == 0) pr0 = pr; else if (hl == 1) pr1 = pr; else pr2 = pr;
            }
            #pragma unroll 8
            for (int kk = 0; kk < 32; ++kk) {
                float v0 = sv[kk][lane], v1 = sv[kk][lane+32];
                float pa = __shfl_sync(0xffffffffu, pr0, kk);
                float pb = __shfl_sync(0xffffffffu, pr1, kk);
                float pc = __shfl_sync(0xffffffffu, pr2, kk);
                a0[qi*3+0] = fmaf(pa, v0, a0[qi*3+0]);
                a1[qi*3+0] = fmaf(pa, v1, a1[qi*3+0]);
                a0[qi*3+1] = fmaf(pb, v0, a0[qi*3+1]);
                a1[qi*3+1] = fmaf(pb, v1, a1[qi*3+1]);
                a0[qi*3+2] = fmaf(pc, v0, a0[qi*3+2]);
                a1[qi*3+2] = fmaf(pc, v1, a1[qi*3+2]);
            }
        }
        __syncthreads();
    }

    #pragma unroll
    for (int qi = 0; qi < 4; ++qi) {
        #pragma unroll
        for (int hl = 0; hl < 3; ++hl) {
            int p = qi*3 + hl;
            size_t off = (size_t)(b*TT + q0 + warp*4 + qi)*DD + (g*3 + hl)*HDD;
            float inv = 1.0f / l[p];
            split_store1(a0[p]*inv, &g_yh[off + lane],      &g_yl[off + lane]);
            split_store1(a1[p]*inv, &g_yh[off + lane + 32], &g_yl[off + lane + 32]);
        }
    }
}

// ------------------------------------------------------------------
// host launcher
// ------------------------------------------------------------------
extern "C" void kernel_launch(void* const* d_in, const int* in_sizes, int n_in,
                              void* d_out, int out_size) {
    (void)in_sizes; (void)n_in; (void)out_size;
    const int*   idx    = (const int*)  d_in[0];
    const float* wte    = (const float*)d_in[1];
    const float* Wq     = (const float*)d_in[2];
    const float* Wk     = (const float*)d_in[3];
    const float* Wv     = (const float*)d_in[4];
    const float* Wo     = (const float*)d_in[5];
    const float* Wfc    = (const float*)d_in[6];
    const float* Wproj  = (const float*)d_in[7];
    const float* vetab  = (const float*)d_in[8];
    const float* vegate = (const float*)d_in[9];
    const float* rl     = (const float*)d_in[10];
    const float* xl     = (const float*)d_in[11];
    const float* lm     = (const float*)d_in[12];
    float* out = (float*)d_out;

    float *px, *pqkv;
    bf16 *pxnh, *pxnl, *pyh, *pyl, *phh, *phl;
    bf16 *pwqkvh, *pwqkvl, *pwoh, *pwol, *pwfch, *pwfcl, *pwprh, *pwprl, *plmh, *plml;
    cudaGetSymbolAddress((void**)&px,    g_x);
    cudaGetSymbolAddress((void**)&pqkv,  g_qkv);
    cudaGetSymbolAddress((void**)&pxnh,  g_xnh);
    cudaGetSymbolAddress((void**)&pxnl,  g_xnl);
    cudaGetSymbolAddress((void**)&pyh,   g_yh);
    cudaGetSymbolAddress((void**)&pyl,   g_yl);
    cudaGetSymbolAddress((void**)&phh,   g_hh);
    cudaGetSymbolAddress((void**)&phl,   g_hl);
    cudaGetSymbolAddress((void**)&pwqkvh,g_wqkvh);
    cudaGetSymbolAddress((void**)&pwqkvl,g_wqkvl);
    cudaGetSymbolAddress((void**)&pwoh,  g_woh);
    cudaGetSymbolAddress((void**)&pwol,  g_wol);
    cudaGetSymbolAddress((void**)&pwfch, g_wfch);
    cudaGetSymbolAddress((void**)&pwfcl, g_wfcl);
    cudaGetSymbolAddress((void**)&pwprh, g_wprh);
    cudaGetSymbolAddress((void**)&pwprl, g_wprl);
    cudaGetSymbolAddress((void**)&plmh,  g_lmh);
    cudaGetSymbolAddress((void**)&plml,  g_lml);

    cudaFuncSetAttribute(gemm_lm_kernel<0>, cudaFuncAttributeMaxDynamicSharedMemorySize, GSMB);
    cudaFuncSetAttribute(gemm_lm_kernel<1>, cudaFuncAttributeMaxDynamicSharedMemorySize, GSMB);
    cudaFuncSetAttribute(gemm_lm_kernel<2>, cudaFuncAttributeMaxDynamicSharedMemorySize, GSMB);
    cudaFuncSetAttribute(gemm_lm_kernel<3>, cudaFuncAttributeMaxDynamicSharedMemorySize, GSMB);

    const int windows[LLAY] = {TT/2, TT, TT/2, TT, TT/2, TT};
    bf16* nb = (bf16*)0;
    int n4;

    // launches 1-3, then the profiled QKV GEMM at launch 4
    n4 = LLAY*QKVW*DD/4;  pack_split_qkv<<<(n4+255)/256, 256>>>(Wq, Wk, Wv);     // 1
    embed_norm_kernel<<<RR, 256>>>(idx, wte);                                    // 2
    resid_norm_kernel<<<RR, 256>>>(rl, xl, 0);                                   // 3
    gemm_lm_kernel<0><<<dim3(QKVW/128, RR/128), 256, GSMB>>>(                    // 4
        pxnh, pxnl, pwqkvh, pwqkvl, pqkv, nb, nb, RR, QKVW, DD);

    // remaining weight splits
    n4 = LLAY*DD*DD/4;    split_kernel<<<(n4+255)/256, 256>>>(Wo,    pwoh,  pwol,  n4);
    n4 = LLAY*FF*DD/4;    split_kernel<<<(n4+255)/256, 256>>>(Wfc,   pwfch, pwfcl, n4);
    n4 = LLAY*DD*FF/4;    split_kernel<<<(n4+255)/256, 256>>>(Wproj, pwprh, pwprl, n4);
    n4 = VV*DD/4;         split_kernel<<<(n4+255)/256, 256>>>(lm,    plmh,  plml,  n4);

    for (int i = 0; i < LLAY; ++i) {
        if (i > 0) {
            resid_norm_kernel<<<RR, 256>>>(rl, xl, i);
            gemm_lm_kernel<0><<<dim3(QKVW/128, RR/128), 256, GSMB>>>(
                pxnh, pxnl, pwqkvh + (size_t)i*QKVW*DD, pwqkvl + (size_t)i*QKVW*DD,
                pqkv, nb, nb, RR, QKVW, DD);
        }

        int slot = (i == 1) ? 0 : (i == 3) ? 1 : (i == 5) ? 2 : -1;
        if (slot >= 0)
            ve_kernel<<<RR, 256>>>(idx, vetab + (size_t)slot*VV*256,
                                   vegate + (size_t)slot*KVHH*32);

        rope_norm_kernel<<<(RR*HH)/8,   256>>>(pqkv, HH,   0);
        rope_norm_kernel<<<(RR*KVHH)/8, 256>>>(pqkv, KVHH, DD);

        attn_kernel<<<BB*KVHH*(TT/QT), 256>>>(windows[i]);

        gemm_lm_kernel<1><<<dim3(DD/128, RR/128), 256, GSMB>>>(
            pyh, pyl, pwoh + (size_t)i*DD*DD, pwol + (size_t)i*DD*DD,
            px, nb, nb, RR, DD, DD);

        resid_norm_kernel<<<RR, 256>>>(rl, xl, -1);

        gemm_lm_kernel<2><<<dim3(FF/128, RR/128), 256, GSMB>>>(
            pxnh, pxnl, pwfch + (size_t)i*FF*DD, pwfcl + (size_t)i*FF*DD,
            px, phh, phl, RR, FF, DD);

        gemm_lm_kernel<1><<<dim3(DD/128, RR/128), 256, GSMB>>>(
            phh, phl, pwprh + (size_t)i*DD*FF, pwprl + (size_t)i*DD*FF,
            px, nb, nb, RR, DD, FF);
    }

    resid_norm_kernel<<<RR, 256>>>(rl, xl, -1);
    gemm_lm_kernel<3><<<dim3(VV/128, RR/128), 256, GSMB>>>(
        pxnh, pxnl, plmh, plml, out, nb, nb, RR, VV, DD);
}